// round 12
// baseline (speedup 1.0000x reference)
#include <cuda_runtime.h>
#include <cuda_bf16.h>
#include <math.h>
#include <stdint.h>

#define BATCH 4
#define SEQ   2048
#define HID   512
#define DFF   2048
#define NLAYER 4
#define NHEAD 4
#define DHEAD 128
#define WINDOW 606
#define KTRUE 30
#define NTOK  (BATCH*SEQ)
#define LN_EPS 1e-5f
#define SM_SCALE 0.08838834764831845f

// ---- scratch ----
__device__ float g_x[NTOK*HID];
__device__ float g_f32[NTOK*3*HID];
__device__ float g_t2[NTOK*HID];
__device__ float g_small[NTOK*16];
__device__ float g_yhat[NTOK*8];
__device__ __nv_bfloat16 g_qkv16[NTOK*3*HID];
__device__ __nv_bfloat16 g_x16[NTOK*HID];
__device__ __nv_bfloat16 g_attn16[NTOK*HID];
__device__ __nv_bfloat16 g_mid16[NTOK*DFF];
#define OFF_QKV 0
#define OFF_OUT (OFF_QKV + 4*1536*512)
#define OFF_FF1 (OFF_OUT + 4*512*512)
#define OFF_FF2 (OFF_FF1 + 4*2048*512)
#define OFF_XM1 (OFF_FF2 + 4*512*2048)
#define OFF_ME2 (OFF_XM1 + 512*512)
#define WT_TOTAL (OFF_ME2 + 512*512)
__device__ __nv_bfloat16 g_wt[WT_TOTAL];

__device__ __forceinline__ float gelu_exact(float v) {
    return 0.5f * v * (1.0f + erff(v * 0.7071067811865475f));
}
__device__ __forceinline__ uint32_t smem_u32(const void* p) {
    uint32_t a;
    asm("{ .reg .u64 t; cvta.to.shared.u64 t, %1; cvt.u32.u64 %0, t; }" : "=r"(a) : "l"(p));
    return a;
}
__device__ __forceinline__ void cp16(uint32_t d, const void* s) {
    asm volatile("cp.async.cg.shared.global [%0], [%1], 16;" :: "r"(d), "l"(s));
}
#define CP_COMMIT() asm volatile("cp.async.commit_group;" ::: "memory")
#define CP_WAIT1()  asm volatile("cp.async.wait_group 1;" ::: "memory")
#define CP_WAIT0()  asm volatile("cp.async.wait_group 0;" ::: "memory")

__device__ __forceinline__ void ldsm_x4(uint32_t& r0, uint32_t& r1, uint32_t& r2, uint32_t& r3,
                                        uint32_t addr) {
    asm volatile("ldmatrix.sync.aligned.m8n8.x4.shared.b16 {%0,%1,%2,%3}, [%4];"
        : "=r"(r0), "=r"(r1), "=r"(r2), "=r"(r3) : "r"(addr));
}
__device__ __forceinline__ void ldsm_x4_t(uint32_t& r0, uint32_t& r1, uint32_t& r2, uint32_t& r3,
                                          uint32_t addr) {
    asm volatile("ldmatrix.sync.aligned.m8n8.x4.trans.shared.b16 {%0,%1,%2,%3}, [%4];"
        : "=r"(r0), "=r"(r1), "=r"(r2), "=r"(r3) : "r"(addr));
}
__device__ __forceinline__ void mma16816(float* d, const uint32_t* a, uint32_t b0, uint32_t b1) {
    asm volatile("mma.sync.aligned.m16n8k16.row.col.f32.bf16.bf16.f32 "
        "{%0,%1,%2,%3}, {%4,%5,%6,%7}, {%8,%9}, {%0,%1,%2,%3};"
        : "+f"(d[0]), "+f"(d[1]), "+f"(d[2]), "+f"(d[3])
        : "r"(a[0]), "r"(a[1]), "r"(a[2]), "r"(a[3]), "r"(b0), "r"(b1));
}
__device__ __forceinline__ uint32_t packbf(float lo, float hi) {
    uint32_t d;
    asm("cvt.rn.bf16x2.f32 %0, %1, %2;" : "=r"(d) : "f"(hi), "f"(lo));
    return d;
}

extern __shared__ char dynsm[];

// ---- weight transpose: Wt[n][k] = bf16(W[k][n]) ----
__global__ void wtrans(const float* __restrict__ W, __nv_bfloat16* __restrict__ Wt, int K, int N) {
    __shared__ float t[32][33];
    size_t ws = (size_t)K*N;
    const float* Wl = W + blockIdx.z*ws;
    __nv_bfloat16* Wtl = Wt + blockIdx.z*ws;
    int k0 = blockIdx.x*32, n0 = blockIdx.y*32;
    for (int i = threadIdx.y; i < 32; i += 8)
        t[i][threadIdx.x] = Wl[(size_t)(k0+i)*N + n0 + threadIdx.x];
    __syncthreads();
    for (int i = threadIdx.y; i < 32; i += 8)
        Wtl[(size_t)(n0+i)*K + k0 + threadIdx.x] = __float2bfloat16(t[threadIdx.x][i]);
}

// ---- embed (dual write) ----
__global__ void embed_kernel(const float* __restrict__ u, const float* __restrict__ y,
                             const float* __restrict__ W_in, const float* __restrict__ b_in,
                             float* __restrict__ x, __nv_bfloat16* __restrict__ x16) {
    int n = blockIdx.x, c = threadIdx.x;
    int b = n >> 11, t = n & (SEQ - 1);
    __shared__ float ua[24];
    if (c < 8)       ua[c] = u[(size_t)(b*8 + c)*SEQ + t];
    else if (c < 16) ua[c] = 0.0f;
    else if (c < 24) ua[c] = (t < KTRUE) ? y[(size_t)(b*8 + (c-16))*SEQ + t] : 0.0f;
    __syncthreads();
    float s = b_in[c];
    #pragma unroll
    for (int k = 0; k < 24; k++) s = fmaf(ua[k], W_in[k*HID + c], s);
    float div = __expf(-9.210340371976184f * (float)(c & ~1) / (float)HID);
    float ang = (float)t * div;
    s += (c & 1) ? cosf(ang) : sinf(ang);
    x[(size_t)n*HID + c] = s;
    x16[(size_t)n*HID + c] = __float2bfloat16(s);
}

// ---- hand-rolled bf16 mma GEMM, 3-stage cp.async pipeline, TK=64 ----
// block 128x128, 8 warps 4(m)x2(n), warp tile 32x64; K-chunks of 64, 3 stages (2 in flight).
#define TK 64
#define WLD 72
#define STG_AB (128*WLD*2)               // 18432 bytes per matrix per stage
#define STG_B  (2*STG_AB)                // 36864 per stage (A then B)
#define GEMM_SMEM (3*STG_B)              // 110592
__global__ __launch_bounds__(256, 2) void gemm_bf16(
    const __nv_bfloat16* __restrict__ A, const __nv_bfloat16* __restrict__ B,
    const float* __restrict__ bias, float* __restrict__ C32,
    __nv_bfloat16* __restrict__ C16, int N, int K, int gelu) {
    const int tid = threadIdx.x;
    const int wid = tid >> 5, lane = tid & 31;
    const int wm = wid >> 1, wn = wid & 1;
    const int bm = blockIdx.y*128, bn = blockIdx.x*128;
    const uint32_t sbase = smem_u32(dynsm);

    float d[2][8][4];
    #pragma unroll
    for (int i = 0; i < 2; i++)
        #pragma unroll
        for (int j = 0; j < 8; j++) { d[i][j][0]=0; d[i][j][1]=0; d[i][j][2]=0; d[i][j][3]=0; }

    const int lr = tid >> 1, lc0 = (tid & 1)*32;
    const int nch = K / TK;
    const __nv_bfloat16* gA = A + (size_t)(bm+lr)*K + lc0;
    const __nv_bfloat16* gB = B + (size_t)(bn+lr)*K + lc0;
    const uint32_t soff = (uint32_t)(lr*WLD + lc0)*2;

    const int arow8 = ((lane >> 3) & 1)*8 + (lane & 7);
    const int acolb = (lane >> 4)*8;
    const int brow  = ((lane >> 4) & 1)*8 + (lane & 7);
    const int bcol  = ((lane >> 3) & 1)*8;

    // prologue: chunks 0,1 -> stages 0,1 (one commit group each)
    #pragma unroll
    for (int pc = 0; pc < 2; pc++) {
        uint32_t ua = sbase + pc*STG_B + soff;
        uint32_t ub = ua + STG_AB;
        const __nv_bfloat16* pa = gA + pc*TK;
        const __nv_bfloat16* pb = gB + pc*TK;
        #pragma unroll
        for (int q = 0; q < 4; q++) { cp16(ua + q*16, pa + q*8); cp16(ub + q*16, pb + q*8); }
        CP_COMMIT();
    }
    // stage index cycles mod 3
    int stg = 0, pstg = 2;
    for (int ch = 0; ch < nch; ch++) {
        CP_WAIT1();            // chunk ch landed (only ch+1's group may be pending)
        __syncthreads();       // protects reuse of stage pstg (last read in iteration ch-1)
        if (ch + 2 < nch) {
            uint32_t ua = sbase + (uint32_t)pstg*STG_B + soff;
            uint32_t ub = ua + STG_AB;
            const __nv_bfloat16* pa = gA + (ch+2)*TK;
            const __nv_bfloat16* pb = gB + (ch+2)*TK;
            #pragma unroll
            for (int q = 0; q < 4; q++) { cp16(ua + q*16, pa + q*8); cp16(ub + q*16, pb + q*8); }
        }
        CP_COMMIT();           // always one group per iteration (possibly empty)
        const uint32_t Asb = sbase + (uint32_t)stg*STG_B;
        const uint32_t Bsb = Asb + STG_AB;
        #pragma unroll
        for (int ks = 0; ks < 4; ks++) {
            uint32_t a[2][4];
            #pragma unroll
            for (int mf = 0; mf < 2; mf++)
                ldsm_x4(a[mf][0], a[mf][1], a[mf][2], a[mf][3],
                        Asb + (uint32_t)((wm*32 + mf*16 + arow8)*WLD + ks*16 + acolb)*2);
            #pragma unroll
            for (int nf4 = 0; nf4 < 4; nf4++) {
                uint32_t r0, r1, r2, r3;
                ldsm_x4(r0, r1, r2, r3,
                        Bsb + (uint32_t)((wn*64 + nf4*16 + brow)*WLD + ks*16 + bcol)*2);
                mma16816(d[0][2*nf4],   a[0], r0, r1);
                mma16816(d[0][2*nf4+1], a[0], r2, r3);
                mma16816(d[1][2*nf4],   a[1], r0, r1);
                mma16816(d[1][2*nf4+1], a[1], r2, r3);
            }
        }
        pstg = stg;
        stg = (stg + 1 == 3) ? 0 : stg + 1;
    }
    // direct-register epilogue
    const int g = lane >> 2, tg = lane & 3;
    #pragma unroll
    for (int mf = 0; mf < 2; mf++) {
        #pragma unroll
        for (int half = 0; half < 2; half++) {
            int grow = bm + wm*32 + mf*16 + half*8 + g;
            #pragma unroll
            for (int nf = 0; nf < 8; nf++) {
                int gcol = bn + wn*64 + nf*8 + tg*2;
                float2 bv = *(const float2*)(bias + gcol);
                float v0 = d[mf][nf][half*2+0] + bv.x;
                float v1 = d[mf][nf][half*2+1] + bv.y;
                if (gelu) { v0 = gelu_exact(v0); v1 = gelu_exact(v1); }
                if (C32) {
                    float2 o = {v0, v1};
                    *(float2*)(C32 + (size_t)grow*N + gcol) = o;
                }
                if (C16) *(uint32_t*)(C16 + (size_t)grow*N + gcol) = packbf(v0, v1);
            }
        }
    }
}

// ---- naive fp32 gemm for tiny head shapes ----
__global__ void gemm_naive(const float* __restrict__ A, const float* __restrict__ W,
                           const float* __restrict__ bias, float* __restrict__ Cf,
                           __nv_bfloat16* __restrict__ Cb, int N, int K, int gelu) {
    int idx = blockIdx.x*256 + threadIdx.x;
    int row = idx / N, col = idx - row*N;
    float s = bias[col];
    const float* a = A + (size_t)row*K;
    for (int k = 0; k < K; k++) s = fmaf(a[k], W[(size_t)k*N + col], s);
    if (gelu) s = gelu_exact(s);
    if (Cf) Cf[idx] = s;
    if (Cb) Cb[idx] = __float2bfloat16(s);
}

// ---- flash v4: FA2-style mma.m16n8k16 bf16, QT=128, KC=64 ----
#define FQT 128
#define FKC 64
#define FQP 136
#define F4_K 34816
#define F4_V 52224
#define FLASH4_SMEM 69632

__global__ __launch_bounds__(256) void flash4(const __nv_bfloat16* __restrict__ qkv,
                                              __nv_bfloat16* __restrict__ out16) {
    __nv_bfloat16* Qs = (__nv_bfloat16*)dynsm;
    __nv_bfloat16* Ks = (__nv_bfloat16*)(dynsm + F4_K);
    __nv_bfloat16* Vs = (__nv_bfloat16*)(dynsm + F4_V);
    const int tid = threadIdx.x, wid = tid >> 5, lane = tid & 31;
    const int g = lane >> 2, tg = lane & 3;
    const int n0 = blockIdx.x*FQT, hh = blockIdx.y;
    const int t0 = n0 & (SEQ - 1), bb = n0 >> 11;
    const int wrow = wid*16;

    {
        int r = tid >> 1, c0 = (tid & 1)*64;
        const __nv_bfloat16* qp = qkv + (size_t)(n0 + r)*1536 + hh*DHEAD + c0;
        __nv_bfloat16* qd = Qs + r*FQP + c0;
        #pragma unroll
        for (int q = 0; q < 8; q++) *(uint4*)(qd + q*8) = *(const uint4*)(qp + q*8);
    }
    __syncthreads();
    uint32_t aq[8][4];
    {
        int row = wrow + ((lane >> 3) & 1)*8 + (lane & 7);
        int colb = (lane >> 4)*8;
        #pragma unroll
        for (int s = 0; s < 8; s++)
            ldsm_x4(aq[s][0], aq[s][1], aq[s][2], aq[s][3],
                    smem_u32(Qs + row*FQP + s*16 + colb));
    }

    float o[16][4];
    #pragma unroll
    for (int f = 0; f < 16; f++) { o[f][0]=0; o[f][1]=0; o[f][2]=0; o[f][3]=0; }
    float m0 = -1e30f, m1 = -1e30f, l0 = 0.0f, l1 = 0.0f;
    const int tr0 = t0 + wrow + g, tr1 = tr0 + 8;

    int jstart = t0 - (WINDOW - 1); if (jstart < 0) jstart = 0;
    const int tmax = t0 + FQT - 1;

    for (int jc = jstart; jc <= tmax; jc += FKC) {
        __syncthreads();
        {
            int r = tid >> 2, c0 = (tid & 3)*32;
            int ja = jc + r; if (ja > tmax) ja = tmax;
            const __nv_bfloat16* kp = qkv + (size_t)((bb << 11) + ja)*1536 + HID + hh*DHEAD + c0;
            __nv_bfloat16* kd = Ks + r*FQP + c0;
            __nv_bfloat16* vd = Vs + r*FQP + c0;
            #pragma unroll
            for (int q = 0; q < 4; q++) {
                *(uint4*)(kd + q*8) = *(const uint4*)(kp + q*8);
                *(uint4*)(vd + q*8) = *(const uint4*)(kp + HID + q*8);
            }
        }
        __syncthreads();

        float sc[8][4];
        #pragma unroll
        for (int f = 0; f < 8; f++) { sc[f][0]=0; sc[f][1]=0; sc[f][2]=0; sc[f][3]=0; }
        {
            int krow_b = ((lane >> 4) & 1)*8 + (lane & 7);
            int kcol_b = ((lane >> 3) & 1)*8;
            #pragma unroll
            for (int ks = 0; ks < 8; ks++) {
                #pragma unroll
                for (int ng = 0; ng < 4; ng++) {
                    uint32_t r0, r1, r2, r3;
                    ldsm_x4(r0, r1, r2, r3,
                            smem_u32(Ks + (ng*16 + krow_b)*FQP + ks*16 + kcol_b));
                    mma16816(sc[2*ng],   aq[ks], r0, r1);
                    mma16816(sc[2*ng+1], aq[ks], r2, r3);
                }
            }
        }

        float r0max = -1e30f, r1max = -1e30f;
        #pragma unroll
        for (int f = 0; f < 8; f++) {
            int jb = jc + f*8 + tg*2;
            #pragma unroll
            for (int c = 0; c < 2; c++) {
                int ja = jb + c;
                bool ok0 = (ja <= tr0) && (ja > tr0 - WINDOW);
                bool ok1 = (ja <= tr1) && (ja > tr1 - WINDOW);
                sc[f][c]   = ok0 ? sc[f][c]*SM_SCALE   : -1e30f;
                sc[f][2+c] = ok1 ? sc[f][2+c]*SM_SCALE : -1e30f;
                r0max = fmaxf(r0max, sc[f][c]);
                r1max = fmaxf(r1max, sc[f][2+c]);
            }
        }
        r0max = fmaxf(r0max, __shfl_xor_sync(0xffffffffu, r0max, 1));
        r0max = fmaxf(r0max, __shfl_xor_sync(0xffffffffu, r0max, 2));
        r1max = fmaxf(r1max, __shfl_xor_sync(0xffffffffu, r1max, 1));
        r1max = fmaxf(r1max, __shfl_xor_sync(0xffffffffu, r1max, 2));
        float mc0 = fmaxf(m0, r0max), mc1 = fmaxf(m1, r1max);
        float ls0 = 0.0f, ls1 = 0.0f;
        #pragma unroll
        for (int f = 0; f < 8; f++) {
            #pragma unroll
            for (int c = 0; c < 2; c++) {
                float p0 = (sc[f][c]   <= -1e29f) ? 0.0f : __expf(sc[f][c]   - mc0);
                float p1 = (sc[f][2+c] <= -1e29f) ? 0.0f : __expf(sc[f][2+c] - mc1);
                sc[f][c] = p0; sc[f][2+c] = p1;
                ls0 += p0; ls1 += p1;
            }
        }
        ls0 += __shfl_xor_sync(0xffffffffu, ls0, 1);
        ls0 += __shfl_xor_sync(0xffffffffu, ls0, 2);
        ls1 += __shfl_xor_sync(0xffffffffu, ls1, 1);
        ls1 += __shfl_xor_sync(0xffffffffu, ls1, 2);
        float s0 = __expf(m0 - mc0), s1 = __expf(m1 - mc1);
        l0 = l0*s0 + ls0; l1 = l1*s1 + ls1;
        m0 = mc0; m1 = mc1;

        #pragma unroll
        for (int f = 0; f < 16; f++) {
            o[f][0] *= s0; o[f][1] *= s0; o[f][2] *= s1; o[f][3] *= s1;
        }
        uint32_t pa[4][4];
        #pragma unroll
        for (int s = 0; s < 4; s++) {
            pa[s][0] = packbf(sc[2*s][0],   sc[2*s][1]);
            pa[s][1] = packbf(sc[2*s][2],   sc[2*s][3]);
            pa[s][2] = packbf(sc[2*s+1][0], sc[2*s+1][1]);
            pa[s][3] = packbf(sc[2*s+1][2], sc[2*s+1][3]);
        }
        {
            int vrow_b = ((lane >> 3) & 1)*8 + (lane & 7);
            int vcol_b = (lane >> 4)*8;
            #pragma unroll
            for (int s = 0; s < 4; s++) {
                #pragma unroll
                for (int ng = 0; ng < 8; ng++) {
                    uint32_t r0, r1, r2, r3;
                    ldsm_x4_t(r0, r1, r2, r3,
                              smem_u32(Vs + (s*16 + vrow_b)*FQP + ng*16 + vcol_b));
                    mma16816(o[2*ng],   pa[s], r0, r1);
                    mma16816(o[2*ng+1], pa[s], r2, r3);
                }
            }
        }
    }

    float inv0 = 1.0f / l0, inv1 = 1.0f / l1;
    __nv_bfloat16* ob0 = out16 + (size_t)(n0 + wrow + g)*HID + hh*DHEAD + tg*2;
    __nv_bfloat16* ob1 = out16 + (size_t)(n0 + wrow + 8 + g)*HID + hh*DHEAD + tg*2;
    #pragma unroll
    for (int f = 0; f < 16; f++) {
        *(uint32_t*)(ob0 + f*8) = packbf(o[f][0]*inv0, o[f][1]*inv0);
        *(uint32_t*)(ob1 + f*8) = packbf(o[f][2]*inv1, o[f][3]*inv1);
    }
}

// ---- residual + LayerNorm (dual write) ----
__global__ __launch_bounds__(256) void ln_kernel(float* __restrict__ x,
                                                 const float* __restrict__ add,
                                                 const float* __restrict__ g,
                                                 const float* __restrict__ b,
                                                 __nv_bfloat16* __restrict__ x16) {
    const int n = blockIdx.x, tid = threadIdx.x;
    const int c0 = tid, c1 = tid + 256;
    float v0 = x[(size_t)n*HID + c0];
    float v1 = x[(size_t)n*HID + c1];
    if (add) { v0 += add[(size_t)n*HID + c0]; v1 += add[(size_t)n*HID + c1]; }
    float s = v0 + v1, sq = v0*v0 + v1*v1;
    #pragma unroll
    for (int o = 16; o > 0; o >>= 1) {
        s  += __shfl_xor_sync(0xffffffffu, s,  o);
        sq += __shfl_xor_sync(0xffffffffu, sq, o);
    }
    __shared__ float ss[8], qq[8], shm, shr;
    int w = tid >> 5;
    if ((tid & 31) == 0) { ss[w] = s; qq[w] = sq; }
    __syncthreads();
    if (tid == 0) {
        float S = 0, Q = 0;
        #pragma unroll
        for (int i = 0; i < 8; i++) { S += ss[i]; Q += qq[i]; }
        float mean = S * (1.0f/512.0f);
        shm = mean;
        shr = rsqrtf(Q * (1.0f/512.0f) - mean*mean + LN_EPS);
    }
    __syncthreads();
    float mean = shm, rstd = shr;
    float o0 = (v0 - mean) * rstd * g[c0] + b[c0];
    float o1 = (v1 - mean) * rstd * g[c1] + b[c1];
    x[(size_t)n*HID + c0] = o0;
    x[(size_t)n*HID + c1] = o1;
    x16[(size_t)n*HID + c0] = __float2bfloat16(o0);
    x16[(size_t)n*HID + c1] = __float2bfloat16(o1);
}

// ---- loss ----
__global__ __launch_bounds__(1024) void loss_kernel(const float* __restrict__ yhat,
                                                    const float* __restrict__ y,
                                                    float* __restrict__ out) {
    float s = 0.0f;
    for (int e = threadIdx.x; e < NTOK*8; e += 1024) {
        int n = e >> 3, d = e & 7;
        int b = n >> 11, t = n & (SEQ - 1);
        float diff = yhat[e] - y[(size_t)(b*8 + d)*SEQ + t];
        s = fmaf(diff, diff, s);
    }
    #pragma unroll
    for (int o = 16; o > 0; o >>= 1) s += __shfl_xor_sync(0xffffffffu, s, o);
    __shared__ float red[32];
    int w = threadIdx.x >> 5;
    if ((threadIdx.x & 31) == 0) red[w] = s;
    __syncthreads();
    if (threadIdx.x == 0) {
        float tot = 0;
        #pragma unroll
        for (int i = 0; i < 32; i++) tot += red[i];
        out[0] = tot;
    }
}

// ---- host ----
static inline void run_wm(const __nv_bfloat16* A, const __nv_bfloat16* B, const float* bias,
                          float* C32, __nv_bfloat16* C16, int N, int K, int gelu) {
    gemm_bf16<<<dim3(N/128, NTOK/128), 256, GEMM_SMEM>>>(A, B, bias, C32, C16, N, K, gelu);
}

extern "C" void kernel_launch(void* const* d_in, const int* in_sizes, int n_in,
                              void* d_out, int out_size) {
    const float *u = (const float*)d_in[0], *y = (const float*)d_in[1];
    const float *W_in = (const float*)d_in[2], *b_in = (const float*)d_in[3];
    const float *qkv_w = (const float*)d_in[4], *qkv_b = (const float*)d_in[5];
    const float *out_w = (const float*)d_in[6], *out_b = (const float*)d_in[7];
    const float *ff1_w = (const float*)d_in[8], *ff1_b = (const float*)d_in[9];
    const float *ff2_w = (const float*)d_in[10], *ff2_b = (const float*)d_in[11];
    const float *ln1_g = (const float*)d_in[12], *ln1_b = (const float*)d_in[13];
    const float *ln2_g = (const float*)d_in[14], *ln2_b = (const float*)d_in[15];
    const float *lnf_g = (const float*)d_in[16], *lnf_b = (const float*)d_in[17];
    const float *xm1_w = (const float*)d_in[18], *xm1_b = (const float*)d_in[19];
    const float *xm2_w = (const float*)d_in[20], *xm2_b = (const float*)d_in[21];
    const float *me1_w = (const float*)d_in[22], *me1_b = (const float*)d_in[23];
    const float *me2_w = (const float*)d_in[24], *me2_b = (const float*)d_in[25];
    const float *me3_w = (const float*)d_in[26], *me3_b = (const float*)d_in[27];

    static float *px = nullptr, *pf32, *pt2, *psmall, *pyhat;
    static __nv_bfloat16 *pqkv16, *px16, *pattn16, *pmid16, *pwt;
    if (!px) {
        cudaGetSymbolAddress((void**)&px, g_x);
        cudaGetSymbolAddress((void**)&pf32, g_f32);
        cudaGetSymbolAddress((void**)&pt2, g_t2);
        cudaGetSymbolAddress((void**)&psmall, g_small);
        cudaGetSymbolAddress((void**)&pyhat, g_yhat);
        cudaGetSymbolAddress((void**)&pqkv16, g_qkv16);
        cudaGetSymbolAddress((void**)&px16, g_x16);
        cudaGetSymbolAddress((void**)&pattn16, g_attn16);
        cudaGetSymbolAddress((void**)&pmid16, g_mid16);
        cudaGetSymbolAddress((void**)&pwt, g_wt);
        cudaFuncSetAttribute(flash4, cudaFuncAttributeMaxDynamicSharedMemorySize, FLASH4_SMEM);
        cudaFuncSetAttribute(gemm_bf16, cudaFuncAttributeMaxDynamicSharedMemorySize, GEMM_SMEM);
    }

    dim3 tb(32, 8);
    // launch order: #4 = QKV gemm_bf16 (ncu captures process-launch #4)
    wtrans<<<dim3(16, 48, 4), tb>>>(qkv_w, pwt + OFF_QKV, 512, 1536);   // 1
    wtrans<<<dim3(16, 16, 4), tb>>>(out_w, pwt + OFF_OUT, 512, 512);    // 2
    embed_kernel<<<NTOK, HID>>>(u, y, W_in, b_in, px, px16);            // 3

    for (int l = 0; l < NLAYER; l++) {
        run_wm(px16, pwt + OFF_QKV + (size_t)l*1536*512, qkv_b + l*1536, nullptr, pqkv16, 1536, 512, 0);  // 4
        flash4<<<dim3(NTOK/FQT, NHEAD), 256, FLASH4_SMEM>>>(pqkv16, pattn16);
        if (l == 0) {
            wtrans<<<dim3(16, 64, 4), tb>>>(ff1_w, pwt + OFF_FF1, 512, 2048);
            wtrans<<<dim3(64, 16, 4), tb>>>(ff2_w, pwt + OFF_FF2, 2048, 512);
        }
        run_wm(pattn16, pwt + OFF_OUT + (size_t)l*512*512, out_b + l*512, pt2, nullptr, 512, 512, 0);
        ln_kernel<<<NTOK, 256>>>(px, pt2, ln1_g + l*HID, ln1_b + l*HID, px16);
        run_wm(px16, pwt + OFF_FF1 + (size_t)l*512*2048, ff1_b + l*2048, nullptr, pmid16, 2048, 512, 1);
        run_wm(pmid16, pwt + OFF_FF2 + (size_t)l*2048*512, ff2_b + l*512, pt2, nullptr, 512, 2048, 0);
        ln_kernel<<<NTOK, 256>>>(px, pt2, ln2_g + l*HID, ln2_b + l*HID, px16);
    }
    ln_kernel<<<NTOK, 256>>>(px, nullptr, lnf_g, lnf_b, px16);

    wtrans<<<dim3(16, 16, 1), tb>>>(xm1_w, pwt + OFF_XM1, 512, 512);
    wtrans<<<dim3(16, 16, 1), tb>>>(me2_w, pwt + OFF_ME2, 512, 512);
    run_wm(px16, pwt + OFF_XM1, xm1_b, pt2, nullptr, 512, 512, 1);
    gemm_naive<<<NTOK*16/256, 256>>>(pt2, xm2_w, xm2_b, psmall, nullptr, 16, 512, 0);
    gemm_naive<<<NTOK*512/256, 256>>>(psmall, me1_w, me1_b, nullptr, pattn16, 512, 16, 1);
    run_wm(pattn16, pwt + OFF_ME2, me2_b, pf32, nullptr, 512, 512, 1);
    gemm_naive<<<NTOK*8/256, 256>>>(pf32, me3_w, me3_b, pyhat, nullptr, 8, 512, 0);

    loss_kernel<<<1, 1024>>>(pyhat, y, (float*)d_out);
}

// round 13
// speedup vs baseline: 1.0726x; 1.0726x over previous
#include <cuda_runtime.h>
#include <cuda_bf16.h>
#include <math.h>
#include <stdint.h>

#define BATCH 4
#define SEQ   2048
#define HID   512
#define DFF   2048
#define NLAYER 4
#define NHEAD 4
#define DHEAD 128
#define WINDOW 606
#define KTRUE 30
#define NTOK  (BATCH*SEQ)
#define LN_EPS 1e-5f
#define SM_SCALE 0.08838834764831845f

// ---- scratch ----
__device__ float g_x[NTOK*HID];
__device__ float g_f32[NTOK*3*HID];
__device__ float g_t2[NTOK*HID];
__device__ float g_small[NTOK*16];
__device__ float g_yhat[NTOK*8];
__device__ __nv_bfloat16 g_qkv16[NTOK*3*HID];
__device__ __nv_bfloat16 g_x16[NTOK*HID];
__device__ __nv_bfloat16 g_attn16[NTOK*HID];
__device__ __nv_bfloat16 g_mid16[NTOK*DFF];
#define OFF_QKV 0
#define OFF_OUT (OFF_QKV + 4*1536*512)
#define OFF_FF1 (OFF_OUT + 4*512*512)
#define OFF_FF2 (OFF_FF1 + 4*2048*512)
#define OFF_XM1 (OFF_FF2 + 4*512*2048)
#define OFF_ME2 (OFF_XM1 + 512*512)
#define WT_TOTAL (OFF_ME2 + 512*512)
__device__ __nv_bfloat16 g_wt[WT_TOTAL];

__device__ __forceinline__ float gelu_exact(float v) {
    return 0.5f * v * (1.0f + erff(v * 0.7071067811865475f));
}
__device__ __forceinline__ uint32_t smem_u32(const void* p) {
    uint32_t a;
    asm("{ .reg .u64 t; cvta.to.shared.u64 t, %1; cvt.u32.u64 %0, t; }" : "=r"(a) : "l"(p));
    return a;
}
__device__ __forceinline__ void cp16(uint32_t d, const void* s) {
    asm volatile("cp.async.cg.shared.global [%0], [%1], 16;" :: "r"(d), "l"(s));
}
#define CP_COMMIT() asm volatile("cp.async.commit_group;" ::: "memory")
#define CP_WAIT4()  asm volatile("cp.async.wait_group 4;" ::: "memory")

__device__ __forceinline__ void ldsm_x4(uint32_t& r0, uint32_t& r1, uint32_t& r2, uint32_t& r3,
                                        uint32_t addr) {
    asm volatile("ldmatrix.sync.aligned.m8n8.x4.shared.b16 {%0,%1,%2,%3}, [%4];"
        : "=r"(r0), "=r"(r1), "=r"(r2), "=r"(r3) : "r"(addr));
}
__device__ __forceinline__ void ldsm_x4_t(uint32_t& r0, uint32_t& r1, uint32_t& r2, uint32_t& r3,
                                          uint32_t addr) {
    asm volatile("ldmatrix.sync.aligned.m8n8.x4.trans.shared.b16 {%0,%1,%2,%3}, [%4];"
        : "=r"(r0), "=r"(r1), "=r"(r2), "=r"(r3) : "r"(addr));
}
__device__ __forceinline__ void mma16816(float* d, const uint32_t* a, uint32_t b0, uint32_t b1) {
    asm volatile("mma.sync.aligned.m16n8k16.row.col.f32.bf16.bf16.f32 "
        "{%0,%1,%2,%3}, {%4,%5,%6,%7}, {%8,%9}, {%0,%1,%2,%3};"
        : "+f"(d[0]), "+f"(d[1]), "+f"(d[2]), "+f"(d[3])
        : "r"(a[0]), "r"(a[1]), "r"(a[2]), "r"(a[3]), "r"(b0), "r"(b1));
}
__device__ __forceinline__ uint32_t packbf(float lo, float hi) {
    uint32_t d;
    asm("cvt.rn.bf16x2.f32 %0, %1, %2;" : "=r"(d) : "f"(hi), "f"(lo));
    return d;
}

extern __shared__ char dynsm[];

// ---- weight transpose: Wt[n][k] = bf16(W[k][n]) ----
__global__ void wtrans(const float* __restrict__ W, __nv_bfloat16* __restrict__ Wt, int K, int N) {
    __shared__ float t[32][33];
    size_t ws = (size_t)K*N;
    const float* Wl = W + blockIdx.z*ws;
    __nv_bfloat16* Wtl = Wt + blockIdx.z*ws;
    int k0 = blockIdx.x*32, n0 = blockIdx.y*32;
    for (int i = threadIdx.y; i < 32; i += 8)
        t[i][threadIdx.x] = Wl[(size_t)(k0+i)*N + n0 + threadIdx.x];
    __syncthreads();
    for (int i = threadIdx.y; i < 32; i += 8)
        Wtl[(size_t)(n0+i)*K + k0 + threadIdx.x] = __float2bfloat16(t[threadIdx.x][i]);
}

// ---- embed (dual write) ----
__global__ void embed_kernel(const float* __restrict__ u, const float* __restrict__ y,
                             const float* __restrict__ W_in, const float* __restrict__ b_in,
                             float* __restrict__ x, __nv_bfloat16* __restrict__ x16) {
    int n = blockIdx.x, c = threadIdx.x;
    int b = n >> 11, t = n & (SEQ - 1);
    __shared__ float ua[24];
    if (c < 8)       ua[c] = u[(size_t)(b*8 + c)*SEQ + t];
    else if (c < 16) ua[c] = 0.0f;
    else if (c < 24) ua[c] = (t < KTRUE) ? y[(size_t)(b*8 + (c-16))*SEQ + t] : 0.0f;
    __syncthreads();
    float s = b_in[c];
    #pragma unroll
    for (int k = 0; k < 24; k++) s = fmaf(ua[k], W_in[k*HID + c], s);
    float div = __expf(-9.210340371976184f * (float)(c & ~1) / (float)HID);
    float ang = (float)t * div;
    s += (c & 1) ? cosf(ang) : sinf(ang);
    x[(size_t)n*HID + c] = s;
    x16[(size_t)n*HID + c] = __float2bfloat16(s);
}

// ---- hand-rolled bf16 mma GEMM, 5-stage cp.async pipeline, TK=32 ----
// block 128x128, 8 warps 4(m)x2(n), warp tile 32x64; K-chunks of 32, 5 stages (4 in flight).
#define TK 32
#define WLD 40
#define STG_AB (128*WLD*2)               // 10240 bytes per matrix per stage
#define STG_B  (2*STG_AB)                // 20480 per stage (A then B)
#define NSTG 5
#define GEMM_SMEM (NSTG*STG_B)           // 102400
__global__ __launch_bounds__(256, 2) void gemm_bf16(
    const __nv_bfloat16* __restrict__ A, const __nv_bfloat16* __restrict__ B,
    const float* __restrict__ bias, float* __restrict__ C32,
    __nv_bfloat16* __restrict__ C16, int N, int K, int gelu) {
    const int tid = threadIdx.x;
    const int wid = tid >> 5, lane = tid & 31;
    const int wm = wid >> 1, wn = wid & 1;
    const int bm = blockIdx.y*128, bn = blockIdx.x*128;
    const uint32_t sbase = smem_u32(dynsm);

    float d[2][8][4];
    #pragma unroll
    for (int i = 0; i < 2; i++)
        #pragma unroll
        for (int j = 0; j < 8; j++) { d[i][j][0]=0; d[i][j][1]=0; d[i][j][2]=0; d[i][j][3]=0; }

    const int lr = tid >> 1, lc0 = (tid & 1)*16;
    const int nch = K / TK;
    const __nv_bfloat16* gA = A + (size_t)(bm+lr)*K + lc0;
    const __nv_bfloat16* gB = B + (size_t)(bn+lr)*K + lc0;
    const uint32_t soff = (uint32_t)(lr*WLD + lc0)*2;

    const int arow8 = ((lane >> 3) & 1)*8 + (lane & 7);
    const int acolb = (lane >> 4)*8;
    const int brow  = ((lane >> 4) & 1)*8 + (lane & 7);
    const int bcol  = ((lane >> 3) & 1)*8;

    // prologue: chunks 0..3 -> stages 0..3 (one group each)
    #pragma unroll
    for (int pc = 0; pc < 4; pc++) {
        uint32_t ua = sbase + pc*STG_B + soff;
        uint32_t ub = ua + STG_AB;
        const __nv_bfloat16* pa = gA + pc*TK;
        const __nv_bfloat16* pb = gB + pc*TK;
        cp16(ua, pa); cp16(ua + 16, pa + 8);
        cp16(ub, pb); cp16(ub + 16, pb + 8);
        CP_COMMIT();
    }
    int stg = 0, wstg = 4;    // compute stage, write stage
    for (int ch = 0; ch < nch; ch++) {
        __syncthreads();      // guard: stage wstg was last read during iteration ch-1
        if (ch + 4 < nch) {
            uint32_t ua = sbase + (uint32_t)wstg*STG_B + soff;
            uint32_t ub = ua + STG_AB;
            const __nv_bfloat16* pa = gA + (ch+4)*TK;
            const __nv_bfloat16* pb = gB + (ch+4)*TK;
            cp16(ua, pa); cp16(ua + 16, pa + 8);
            cp16(ub, pb); cp16(ub + 16, pb + 8);
        }
        CP_COMMIT();          // one group per iteration (possibly empty)
        CP_WAIT4();           // committed = ch+5 groups; <=4 pending => chunk ch landed
        const uint32_t Asb = sbase + (uint32_t)stg*STG_B;
        const uint32_t Bsb = Asb + STG_AB;
        #pragma unroll
        for (int ks = 0; ks < 2; ks++) {
            uint32_t a[2][4];
            #pragma unroll
            for (int mf = 0; mf < 2; mf++)
                ldsm_x4(a[mf][0], a[mf][1], a[mf][2], a[mf][3],
                        Asb + (uint32_t)((wm*32 + mf*16 + arow8)*WLD + ks*16 + acolb)*2);
            #pragma unroll
            for (int nf4 = 0; nf4 < 4; nf4++) {
                uint32_t r0, r1, r2, r3;
                ldsm_x4(r0, r1, r2, r3,
                        Bsb + (uint32_t)((wn*64 + nf4*16 + brow)*WLD + ks*16 + bcol)*2);
                mma16816(d[0][2*nf4],   a[0], r0, r1);
                mma16816(d[0][2*nf4+1], a[0], r2, r3);
                mma16816(d[1][2*nf4],   a[1], r0, r1);
                mma16816(d[1][2*nf4+1], a[1], r2, r3);
            }
        }
        wstg = stg;
        stg = (stg + 1 == NSTG) ? 0 : stg + 1;
    }
    // direct-register epilogue
    const int g = lane >> 2, tg = lane & 3;
    #pragma unroll
    for (int mf = 0; mf < 2; mf++) {
        #pragma unroll
        for (int half = 0; half < 2; half++) {
            int grow = bm + wm*32 + mf*16 + half*8 + g;
            #pragma unroll
            for (int nf = 0; nf < 8; nf++) {
                int gcol = bn + wn*64 + nf*8 + tg*2;
                float2 bv = *(const float2*)(bias + gcol);
                float v0 = d[mf][nf][half*2+0] + bv.x;
                float v1 = d[mf][nf][half*2+1] + bv.y;
                if (gelu) { v0 = gelu_exact(v0); v1 = gelu_exact(v1); }
                if (C32) {
                    float2 o = {v0, v1};
                    *(float2*)(C32 + (size_t)grow*N + gcol) = o;
                }
                if (C16) *(uint32_t*)(C16 + (size_t)grow*N + gcol) = packbf(v0, v1);
            }
        }
    }
}

// ---- naive fp32 gemm for tiny head shapes ----
__global__ void gemm_naive(const float* __restrict__ A, const float* __restrict__ W,
                           const float* __restrict__ bias, float* __restrict__ Cf,
                           __nv_bfloat16* __restrict__ Cb, int N, int K, int gelu) {
    int idx = blockIdx.x*256 + threadIdx.x;
    int row = idx / N, col = idx - row*N;
    float s = bias[col];
    const float* a = A + (size_t)row*K;
    for (int k = 0; k < K; k++) s = fmaf(a[k], W[(size_t)k*N + col], s);
    if (gelu) s = gelu_exact(s);
    if (Cf) Cf[idx] = s;
    if (Cb) Cb[idx] = __float2bfloat16(s);
}

// ---- flash v4: FA2-style mma.m16n8k16 bf16, QT=128, KC=64 ----
#define FQT 128
#define FKC 64
#define FQP 136
#define F4_K 34816
#define F4_V 52224
#define FLASH4_SMEM 69632

__global__ __launch_bounds__(256) void flash4(const __nv_bfloat16* __restrict__ qkv,
                                              __nv_bfloat16* __restrict__ out16) {
    __nv_bfloat16* Qs = (__nv_bfloat16*)dynsm;
    __nv_bfloat16* Ks = (__nv_bfloat16*)(dynsm + F4_K);
    __nv_bfloat16* Vs = (__nv_bfloat16*)(dynsm + F4_V);
    const int tid = threadIdx.x, wid = tid >> 5, lane = tid & 31;
    const int g = lane >> 2, tg = lane & 3;
    const int n0 = blockIdx.x*FQT, hh = blockIdx.y;
    const int t0 = n0 & (SEQ - 1), bb = n0 >> 11;
    const int wrow = wid*16;

    {
        int r = tid >> 1, c0 = (tid & 1)*64;
        const __nv_bfloat16* qp = qkv + (size_t)(n0 + r)*1536 + hh*DHEAD + c0;
        __nv_bfloat16* qd = Qs + r*FQP + c0;
        #pragma unroll
        for (int q = 0; q < 8; q++) *(uint4*)(qd + q*8) = *(const uint4*)(qp + q*8);
    }
    __syncthreads();
    uint32_t aq[8][4];
    {
        int row = wrow + ((lane >> 3) & 1)*8 + (lane & 7);
        int colb = (lane >> 4)*8;
        #pragma unroll
        for (int s = 0; s < 8; s++)
            ldsm_x4(aq[s][0], aq[s][1], aq[s][2], aq[s][3],
                    smem_u32(Qs + row*FQP + s*16 + colb));
    }

    float o[16][4];
    #pragma unroll
    for (int f = 0; f < 16; f++) { o[f][0]=0; o[f][1]=0; o[f][2]=0; o[f][3]=0; }
    float m0 = -1e30f, m1 = -1e30f, l0 = 0.0f, l1 = 0.0f;
    const int tr0 = t0 + wrow + g, tr1 = tr0 + 8;

    int jstart = t0 - (WINDOW - 1); if (jstart < 0) jstart = 0;
    const int tmax = t0 + FQT - 1;

    for (int jc = jstart; jc <= tmax; jc += FKC) {
        __syncthreads();
        {
            int r = tid >> 2, c0 = (tid & 3)*32;
            int ja = jc + r; if (ja > tmax) ja = tmax;
            const __nv_bfloat16* kp = qkv + (size_t)((bb << 11) + ja)*1536 + HID + hh*DHEAD + c0;
            __nv_bfloat16* kd = Ks + r*FQP + c0;
            __nv_bfloat16* vd = Vs + r*FQP + c0;
            #pragma unroll
            for (int q = 0; q < 4; q++) {
                *(uint4*)(kd + q*8) = *(const uint4*)(kp + q*8);
                *(uint4*)(vd + q*8) = *(const uint4*)(kp + HID + q*8);
            }
        }
        __syncthreads();

        float sc[8][4];
        #pragma unroll
        for (int f = 0; f < 8; f++) { sc[f][0]=0; sc[f][1]=0; sc[f][2]=0; sc[f][3]=0; }
        {
            int krow_b = ((lane >> 4) & 1)*8 + (lane & 7);
            int kcol_b = ((lane >> 3) & 1)*8;
            #pragma unroll
            for (int ks = 0; ks < 8; ks++) {
                #pragma unroll
                for (int ng = 0; ng < 4; ng++) {
                    uint32_t r0, r1, r2, r3;
                    ldsm_x4(r0, r1, r2, r3,
                            smem_u32(Ks + (ng*16 + krow_b)*FQP + ks*16 + kcol_b));
                    mma16816(sc[2*ng],   aq[ks], r0, r1);
                    mma16816(sc[2*ng+1], aq[ks], r2, r3);
                }
            }
        }

        float r0max = -1e30f, r1max = -1e30f;
        #pragma unroll
        for (int f = 0; f < 8; f++) {
            int jb = jc + f*8 + tg*2;
            #pragma unroll
            for (int c = 0; c < 2; c++) {
                int ja = jb + c;
                bool ok0 = (ja <= tr0) && (ja > tr0 - WINDOW);
                bool ok1 = (ja <= tr1) && (ja > tr1 - WINDOW);
                sc[f][c]   = ok0 ? sc[f][c]*SM_SCALE   : -1e30f;
                sc[f][2+c] = ok1 ? sc[f][2+c]*SM_SCALE : -1e30f;
                r0max = fmaxf(r0max, sc[f][c]);
                r1max = fmaxf(r1max, sc[f][2+c]);
            }
        }
        r0max = fmaxf(r0max, __shfl_xor_sync(0xffffffffu, r0max, 1));
        r0max = fmaxf(r0max, __shfl_xor_sync(0xffffffffu, r0max, 2));
        r1max = fmaxf(r1max, __shfl_xor_sync(0xffffffffu, r1max, 1));
        r1max = fmaxf(r1max, __shfl_xor_sync(0xffffffffu, r1max, 2));
        float mc0 = fmaxf(m0, r0max), mc1 = fmaxf(m1, r1max);
        float ls0 = 0.0f, ls1 = 0.0f;
        #pragma unroll
        for (int f = 0; f < 8; f++) {
            #pragma unroll
            for (int c = 0; c < 2; c++) {
                float p0 = (sc[f][c]   <= -1e29f) ? 0.0f : __expf(sc[f][c]   - mc0);
                float p1 = (sc[f][2+c] <= -1e29f) ? 0.0f : __expf(sc[f][2+c] - mc1);
                sc[f][c] = p0; sc[f][2+c] = p1;
                ls0 += p0; ls1 += p1;
            }
        }
        ls0 += __shfl_xor_sync(0xffffffffu, ls0, 1);
        ls0 += __shfl_xor_sync(0xffffffffu, ls0, 2);
        ls1 += __shfl_xor_sync(0xffffffffu, ls1, 1);
        ls1 += __shfl_xor_sync(0xffffffffu, ls1, 2);
        float s0 = __expf(m0 - mc0), s1 = __expf(m1 - mc1);
        l0 = l0*s0 + ls0; l1 = l1*s1 + ls1;
        m0 = mc0; m1 = mc1;

        #pragma unroll
        for (int f = 0; f < 16; f++) {
            o[f][0] *= s0; o[f][1] *= s0; o[f][2] *= s1; o[f][3] *= s1;
        }
        uint32_t pa[4][4];
        #pragma unroll
        for (int s = 0; s < 4; s++) {
            pa[s][0] = packbf(sc[2*s][0],   sc[2*s][1]);
            pa[s][1] = packbf(sc[2*s][2],   sc[2*s][3]);
            pa[s][2] = packbf(sc[2*s+1][0], sc[2*s+1][1]);
            pa[s][3] = packbf(sc[2*s+1][2], sc[2*s+1][3]);
        }
        {
            int vrow_b = ((lane >> 3) & 1)*8 + (lane & 7);
            int vcol_b = (lane >> 4)*8;
            #pragma unroll
            for (int s = 0; s < 4; s++) {
                #pragma unroll
                for (int ng = 0; ng < 8; ng++) {
                    uint32_t r0, r1, r2, r3;
                    ldsm_x4_t(r0, r1, r2, r3,
                              smem_u32(Vs + (s*16 + vrow_b)*FQP + ng*16 + vcol_b));
                    mma16816(o[2*ng],   pa[s], r0, r1);
                    mma16816(o[2*ng+1], pa[s], r2, r3);
                }
            }
        }
    }

    float inv0 = 1.0f / l0, inv1 = 1.0f / l1;
    __nv_bfloat16* ob0 = out16 + (size_t)(n0 + wrow + g)*HID + hh*DHEAD + tg*2;
    __nv_bfloat16* ob1 = out16 + (size_t)(n0 + wrow + 8 + g)*HID + hh*DHEAD + tg*2;
    #pragma unroll
    for (int f = 0; f < 16; f++) {
        *(uint32_t*)(ob0 + f*8) = packbf(o[f][0]*inv0, o[f][1]*inv0);
        *(uint32_t*)(ob1 + f*8) = packbf(o[f][2]*inv1, o[f][3]*inv1);
    }
}

// ---- residual + LayerNorm (dual write) ----
__global__ __launch_bounds__(256) void ln_kernel(float* __restrict__ x,
                                                 const float* __restrict__ add,
                                                 const float* __restrict__ g,
                                                 const float* __restrict__ b,
                                                 __nv_bfloat16* __restrict__ x16) {
    const int n = blockIdx.x, tid = threadIdx.x;
    const int c0 = tid, c1 = tid + 256;
    float v0 = x[(size_t)n*HID + c0];
    float v1 = x[(size_t)n*HID + c1];
    if (add) { v0 += add[(size_t)n*HID + c0]; v1 += add[(size_t)n*HID + c1]; }
    float s = v0 + v1, sq = v0*v0 + v1*v1;
    #pragma unroll
    for (int o = 16; o > 0; o >>= 1) {
        s  += __shfl_xor_sync(0xffffffffu, s,  o);
        sq += __shfl_xor_sync(0xffffffffu, sq, o);
    }
    __shared__ float ss[8], qq[8], shm, shr;
    int w = tid >> 5;
    if ((tid & 31) == 0) { ss[w] = s; qq[w] = sq; }
    __syncthreads();
    if (tid == 0) {
        float S = 0, Q = 0;
        #pragma unroll
        for (int i = 0; i < 8; i++) { S += ss[i]; Q += qq[i]; }
        float mean = S * (1.0f/512.0f);
        shm = mean;
        shr = rsqrtf(Q * (1.0f/512.0f) - mean*mean + LN_EPS);
    }
    __syncthreads();
    float mean = shm, rstd = shr;
    float o0 = (v0 - mean) * rstd * g[c0] + b[c0];
    float o1 = (v1 - mean) * rstd * g[c1] + b[c1];
    x[(size_t)n*HID + c0] = o0;
    x[(size_t)n*HID + c1] = o1;
    x16[(size_t)n*HID + c0] = __float2bfloat16(o0);
    x16[(size_t)n*HID + c1] = __float2bfloat16(o1);
}

// ---- loss ----
__global__ __launch_bounds__(1024) void loss_kernel(const float* __restrict__ yhat,
                                                    const float* __restrict__ y,
                                                    float* __restrict__ out) {
    float s = 0.0f;
    for (int e = threadIdx.x; e < NTOK*8; e += 1024) {
        int n = e >> 3, d = e & 7;
        int b = n >> 11, t = n & (SEQ - 1);
        float diff = yhat[e] - y[(size_t)(b*8 + d)*SEQ + t];
        s = fmaf(diff, diff, s);
    }
    #pragma unroll
    for (int o = 16; o > 0; o >>= 1) s += __shfl_xor_sync(0xffffffffu, s, o);
    __shared__ float red[32];
    int w = threadIdx.x >> 5;
    if ((threadIdx.x & 31) == 0) red[w] = s;
    __syncthreads();
    if (threadIdx.x == 0) {
        float tot = 0;
        #pragma unroll
        for (int i = 0; i < 32; i++) tot += red[i];
        out[0] = tot;
    }
}

// ---- host ----
static inline void run_wm(const __nv_bfloat16* A, const __nv_bfloat16* B, const float* bias,
                          float* C32, __nv_bfloat16* C16, int N, int K, int gelu) {
    gemm_bf16<<<dim3(N/128, NTOK/128), 256, GEMM_SMEM>>>(A, B, bias, C32, C16, N, K, gelu);
}

extern "C" void kernel_launch(void* const* d_in, const int* in_sizes, int n_in,
                              void* d_out, int out_size) {
    const float *u = (const float*)d_in[0], *y = (const float*)d_in[1];
    const float *W_in = (const float*)d_in[2], *b_in = (const float*)d_in[3];
    const float *qkv_w = (const float*)d_in[4], *qkv_b = (const float*)d_in[5];
    const float *out_w = (const float*)d_in[6], *out_b = (const float*)d_in[7];
    const float *ff1_w = (const float*)d_in[8], *ff1_b = (const float*)d_in[9];
    const float *ff2_w = (const float*)d_in[10], *ff2_b = (const float*)d_in[11];
    const float *ln1_g = (const float*)d_in[12], *ln1_b = (const float*)d_in[13];
    const float *ln2_g = (const float*)d_in[14], *ln2_b = (const float*)d_in[15];
    const float *lnf_g = (const float*)d_in[16], *lnf_b = (const float*)d_in[17];
    const float *xm1_w = (const float*)d_in[18], *xm1_b = (const float*)d_in[19];
    const float *xm2_w = (const float*)d_in[20], *xm2_b = (const float*)d_in[21];
    const float *me1_w = (const float*)d_in[22], *me1_b = (const float*)d_in[23];
    const float *me2_w = (const float*)d_in[24], *me2_b = (const float*)d_in[25];
    const float *me3_w = (const float*)d_in[26], *me3_b = (const float*)d_in[27];

    static float *px = nullptr, *pf32, *pt2, *psmall, *pyhat;
    static __nv_bfloat16 *pqkv16, *px16, *pattn16, *pmid16, *pwt;
    if (!px) {
        cudaGetSymbolAddress((void**)&px, g_x);
        cudaGetSymbolAddress((void**)&pf32, g_f32);
        cudaGetSymbolAddress((void**)&pt2, g_t2);
        cudaGetSymbolAddress((void**)&psmall, g_small);
        cudaGetSymbolAddress((void**)&pyhat, g_yhat);
        cudaGetSymbolAddress((void**)&pqkv16, g_qkv16);
        cudaGetSymbolAddress((void**)&px16, g_x16);
        cudaGetSymbolAddress((void**)&pattn16, g_attn16);
        cudaGetSymbolAddress((void**)&pmid16, g_mid16);
        cudaGetSymbolAddress((void**)&pwt, g_wt);
        cudaFuncSetAttribute(flash4, cudaFuncAttributeMaxDynamicSharedMemorySize, FLASH4_SMEM);
        cudaFuncSetAttribute(gemm_bf16, cudaFuncAttributeMaxDynamicSharedMemorySize, GEMM_SMEM);
    }

    dim3 tb(32, 8);
    // launch order: #4 = QKV gemm_bf16 (ncu captures process-launch #4)
    wtrans<<<dim3(16, 48, 4), tb>>>(qkv_w, pwt + OFF_QKV, 512, 1536);   // 1
    wtrans<<<dim3(16, 16, 4), tb>>>(out_w, pwt + OFF_OUT, 512, 512);    // 2
    embed_kernel<<<NTOK, HID>>>(u, y, W_in, b_in, px, px16);            // 3

    for (int l = 0; l < NLAYER; l++) {
        run_wm(px16, pwt + OFF_QKV + (size_t)l*1536*512, qkv_b + l*1536, nullptr, pqkv16, 1536, 512, 0);  // 4
        flash4<<<dim3(NTOK/FQT, NHEAD), 256, FLASH4_SMEM>>>(pqkv16, pattn16);
        if (l == 0) {
            wtrans<<<dim3(16, 64, 4), tb>>>(ff1_w, pwt + OFF_FF1, 512, 2048);
            wtrans<<<dim3(64, 16, 4), tb>>>(ff2_w, pwt + OFF_FF2, 2048, 512);
        }
        run_wm(pattn16, pwt + OFF_OUT + (size_t)l*512*512, out_b + l*512, pt2, nullptr, 512, 512, 0);
        ln_kernel<<<NTOK, 256>>>(px, pt2, ln1_g + l*HID, ln1_b + l*HID, px16);
        run_wm(px16, pwt + OFF_FF1 + (size_t)l*512*2048, ff1_b + l*2048, nullptr, pmid16, 2048, 512, 1);
        run_wm(pmid16, pwt + OFF_FF2 + (size_t)l*2048*512, ff2_b + l*512, pt2, nullptr, 512, 2048, 0);
        ln_kernel<<<NTOK, 256>>>(px, pt2, ln2_g + l*HID, ln2_b + l*HID, px16);
    }
    ln_kernel<<<NTOK, 256>>>(px, nullptr, lnf_g, lnf_b, px16);

    wtrans<<<dim3(16, 16, 1), tb>>>(xm1_w, pwt + OFF_XM1, 512, 512);
    wtrans<<<dim3(16, 16, 1), tb>>>(me2_w, pwt + OFF_ME2, 512, 512);
    run_wm(px16, pwt + OFF_XM1, xm1_b, pt2, nullptr, 512, 512, 1);
    gemm_naive<<<NTOK*16/256, 256>>>(pt2, xm2_w, xm2_b, psmall, nullptr, 16, 512, 0);
    gemm_naive<<<NTOK*512/256, 256>>>(psmall, me1_w, me1_b, nullptr, pattn16, 512, 16, 1);
    run_wm(pattn16, pwt + OFF_ME2, me2_b, pf32, nullptr, 512, 512, 1);
    gemm_naive<<<NTOK*8/256, 256>>>(pf32, me3_w, me3_b, pyhat, nullptr, 8, 512, 0);

    loss_kernel<<<1, 1024>>>(pyhat, y, (float*)d_out);
}

// round 14
// speedup vs baseline: 1.1218x; 1.0458x over previous
#include <cuda_runtime.h>
#include <cuda_bf16.h>
#include <math.h>
#include <stdint.h>

#define BATCH 4
#define SEQ   2048
#define HID   512
#define DFF   2048
#define NLAYER 4
#define NHEAD 4
#define DHEAD 128
#define WINDOW 606
#define KTRUE 30
#define NTOK  (BATCH*SEQ)
#define LN_EPS 1e-5f
#define SM_SCALE 0.08838834764831845f

// ---- scratch ----
__device__ float g_x[NTOK*HID];
__device__ float g_f32[NTOK*3*HID];
__device__ float g_t2[NTOK*HID];
__device__ float g_small[NTOK*16];
__device__ float g_yhat[NTOK*8];
__device__ __nv_bfloat16 g_qkv16[NTOK*3*HID];
__device__ __nv_bfloat16 g_x16[NTOK*HID];
__device__ __nv_bfloat16 g_attn16[NTOK*HID];
__device__ __nv_bfloat16 g_mid16[NTOK*DFF];
#define OFF_QKV 0
#define OFF_OUT (OFF_QKV + 4*1536*512)
#define OFF_FF1 (OFF_OUT + 4*512*512)
#define OFF_FF2 (OFF_FF1 + 4*2048*512)
#define OFF_XM1 (OFF_FF2 + 4*512*2048)
#define OFF_ME2 (OFF_XM1 + 512*512)
#define WT_TOTAL (OFF_ME2 + 512*512)
__device__ __nv_bfloat16 g_wt[WT_TOTAL];

__device__ __forceinline__ float gelu_exact(float v) {
    return 0.5f * v * (1.0f + erff(v * 0.7071067811865475f));
}
__device__ __forceinline__ uint32_t smem_u32(const void* p) {
    uint32_t a;
    asm("{ .reg .u64 t; cvta.to.shared.u64 t, %1; cvt.u32.u64 %0, t; }" : "=r"(a) : "l"(p));
    return a;
}
__device__ __forceinline__ void cp16(uint32_t d, const void* s) {
    asm volatile("cp.async.cg.shared.global [%0], [%1], 16;" :: "r"(d), "l"(s));
}
#define CP_COMMIT() asm volatile("cp.async.commit_group;" ::: "memory")
#define CP_WAIT1()  asm volatile("cp.async.wait_group 1;" ::: "memory")
#define CP_WAIT4()  asm volatile("cp.async.wait_group 4;" ::: "memory")

__device__ __forceinline__ void ldsm_x4(uint32_t& r0, uint32_t& r1, uint32_t& r2, uint32_t& r3,
                                        uint32_t addr) {
    asm volatile("ldmatrix.sync.aligned.m8n8.x4.shared.b16 {%0,%1,%2,%3}, [%4];"
        : "=r"(r0), "=r"(r1), "=r"(r2), "=r"(r3) : "r"(addr));
}
__device__ __forceinline__ void ldsm_x4_t(uint32_t& r0, uint32_t& r1, uint32_t& r2, uint32_t& r3,
                                          uint32_t addr) {
    asm volatile("ldmatrix.sync.aligned.m8n8.x4.trans.shared.b16 {%0,%1,%2,%3}, [%4];"
        : "=r"(r0), "=r"(r1), "=r"(r2), "=r"(r3) : "r"(addr));
}
__device__ __forceinline__ void mma16816(float* d, const uint32_t* a, uint32_t b0, uint32_t b1) {
    asm volatile("mma.sync.aligned.m16n8k16.row.col.f32.bf16.bf16.f32 "
        "{%0,%1,%2,%3}, {%4,%5,%6,%7}, {%8,%9}, {%0,%1,%2,%3};"
        : "+f"(d[0]), "+f"(d[1]), "+f"(d[2]), "+f"(d[3])
        : "r"(a[0]), "r"(a[1]), "r"(a[2]), "r"(a[3]), "r"(b0), "r"(b1));
}
__device__ __forceinline__ uint32_t packbf(float lo, float hi) {
    uint32_t d;
    asm("cvt.rn.bf16x2.f32 %0, %1, %2;" : "=r"(d) : "f"(hi), "f"(lo));
    return d;
}

extern __shared__ char dynsm[];

// ---- weight transpose: Wt[n][k] = bf16(W[k][n]) ----
__global__ void wtrans(const float* __restrict__ W, __nv_bfloat16* __restrict__ Wt, int K, int N) {
    __shared__ float t[32][33];
    size_t ws = (size_t)K*N;
    const float* Wl = W + blockIdx.z*ws;
    __nv_bfloat16* Wtl = Wt + blockIdx.z*ws;
    int k0 = blockIdx.x*32, n0 = blockIdx.y*32;
    for (int i = threadIdx.y; i < 32; i += 8)
        t[i][threadIdx.x] = Wl[(size_t)(k0+i)*N + n0 + threadIdx.x];
    __syncthreads();
    for (int i = threadIdx.y; i < 32; i += 8)
        Wtl[(size_t)(n0+i)*K + k0 + threadIdx.x] = __float2bfloat16(t[threadIdx.x][i]);
}

// ---- embed (dual write) ----
__global__ void embed_kernel(const float* __restrict__ u, const float* __restrict__ y,
                             const float* __restrict__ W_in, const float* __restrict__ b_in,
                             float* __restrict__ x, __nv_bfloat16* __restrict__ x16) {
    int n = blockIdx.x, c = threadIdx.x;
    int b = n >> 11, t = n & (SEQ - 1);
    __shared__ float ua[24];
    if (c < 8)       ua[c] = u[(size_t)(b*8 + c)*SEQ + t];
    else if (c < 16) ua[c] = 0.0f;
    else if (c < 24) ua[c] = (t < KTRUE) ? y[(size_t)(b*8 + (c-16))*SEQ + t] : 0.0f;
    __syncthreads();
    float s = b_in[c];
    #pragma unroll
    for (int k = 0; k < 24; k++) s = fmaf(ua[k], W_in[k*HID + c], s);
    float div = __expf(-9.210340371976184f * (float)(c & ~1) / (float)HID);
    float ang = (float)t * div;
    s += (c & 1) ? cosf(ang) : sinf(ang);
    x[(size_t)n*HID + c] = s;
    x16[(size_t)n*HID + c] = __float2bfloat16(s);
}

// ---- hand-rolled bf16 mma GEMM, 5-stage cp.async pipeline, TK=32 (R13, frozen) ----
#define TK 32
#define WLD 40
#define STG_AB (128*WLD*2)
#define STG_B  (2*STG_AB)
#define NSTG 5
#define GEMM_SMEM (NSTG*STG_B)           // 102400
__global__ __launch_bounds__(256, 2) void gemm_bf16(
    const __nv_bfloat16* __restrict__ A, const __nv_bfloat16* __restrict__ B,
    const float* __restrict__ bias, float* __restrict__ C32,
    __nv_bfloat16* __restrict__ C16, int N, int K, int gelu) {
    const int tid = threadIdx.x;
    const int wid = tid >> 5, lane = tid & 31;
    const int wm = wid >> 1, wn = wid & 1;
    const int bm = blockIdx.y*128, bn = blockIdx.x*128;
    const uint32_t sbase = smem_u32(dynsm);

    float d[2][8][4];
    #pragma unroll
    for (int i = 0; i < 2; i++)
        #pragma unroll
        for (int j = 0; j < 8; j++) { d[i][j][0]=0; d[i][j][1]=0; d[i][j][2]=0; d[i][j][3]=0; }

    const int lr = tid >> 1, lc0 = (tid & 1)*16;
    const int nch = K / TK;
    const __nv_bfloat16* gA = A + (size_t)(bm+lr)*K + lc0;
    const __nv_bfloat16* gB = B + (size_t)(bn+lr)*K + lc0;
    const uint32_t soff = (uint32_t)(lr*WLD + lc0)*2;

    const int arow8 = ((lane >> 3) & 1)*8 + (lane & 7);
    const int acolb = (lane >> 4)*8;
    const int brow  = ((lane >> 4) & 1)*8 + (lane & 7);
    const int bcol  = ((lane >> 3) & 1)*8;

    #pragma unroll
    for (int pc = 0; pc < 4; pc++) {
        uint32_t ua = sbase + pc*STG_B + soff;
        uint32_t ub = ua + STG_AB;
        const __nv_bfloat16* pa = gA + pc*TK;
        const __nv_bfloat16* pb = gB + pc*TK;
        cp16(ua, pa); cp16(ua + 16, pa + 8);
        cp16(ub, pb); cp16(ub + 16, pb + 8);
        CP_COMMIT();
    }
    int stg = 0, wstg = 4;
    for (int ch = 0; ch < nch; ch++) {
        __syncthreads();
        if (ch + 4 < nch) {
            uint32_t ua = sbase + (uint32_t)wstg*STG_B + soff;
            uint32_t ub = ua + STG_AB;
            const __nv_bfloat16* pa = gA + (ch+4)*TK;
            const __nv_bfloat16* pb = gB + (ch+4)*TK;
            cp16(ua, pa); cp16(ua + 16, pa + 8);
            cp16(ub, pb); cp16(ub + 16, pb + 8);
        }
        CP_COMMIT();
        CP_WAIT4();
        const uint32_t Asb = sbase + (uint32_t)stg*STG_B;
        const uint32_t Bsb = Asb + STG_AB;
        #pragma unroll
        for (int ks = 0; ks < 2; ks++) {
            uint32_t a[2][4];
            #pragma unroll
            for (int mf = 0; mf < 2; mf++)
                ldsm_x4(a[mf][0], a[mf][1], a[mf][2], a[mf][3],
                        Asb + (uint32_t)((wm*32 + mf*16 + arow8)*WLD + ks*16 + acolb)*2);
            #pragma unroll
            for (int nf4 = 0; nf4 < 4; nf4++) {
                uint32_t r0, r1, r2, r3;
                ldsm_x4(r0, r1, r2, r3,
                        Bsb + (uint32_t)((wn*64 + nf4*16 + brow)*WLD + ks*16 + bcol)*2);
                mma16816(d[0][2*nf4],   a[0], r0, r1);
                mma16816(d[0][2*nf4+1], a[0], r2, r3);
                mma16816(d[1][2*nf4],   a[1], r0, r1);
                mma16816(d[1][2*nf4+1], a[1], r2, r3);
            }
        }
        wstg = stg;
        stg = (stg + 1 == NSTG) ? 0 : stg + 1;
    }
    const int g = lane >> 2, tg = lane & 3;
    #pragma unroll
    for (int mf = 0; mf < 2; mf++) {
        #pragma unroll
        for (int half = 0; half < 2; half++) {
            int grow = bm + wm*32 + mf*16 + half*8 + g;
            #pragma unroll
            for (int nf = 0; nf < 8; nf++) {
                int gcol = bn + wn*64 + nf*8 + tg*2;
                float2 bv = *(const float2*)(bias + gcol);
                float v0 = d[mf][nf][half*2+0] + bv.x;
                float v1 = d[mf][nf][half*2+1] + bv.y;
                if (gelu) { v0 = gelu_exact(v0); v1 = gelu_exact(v1); }
                if (C32) {
                    float2 o = {v0, v1};
                    *(float2*)(C32 + (size_t)grow*N + gcol) = o;
                }
                if (C16) *(uint32_t*)(C16 + (size_t)grow*N + gcol) = packbf(v0, v1);
            }
        }
    }
}

// ---- naive fp32 gemm for tiny head shapes ----
__global__ void gemm_naive(const float* __restrict__ A, const float* __restrict__ W,
                           const float* __restrict__ bias, float* __restrict__ Cf,
                           __nv_bfloat16* __restrict__ Cb, int N, int K, int gelu) {
    int idx = blockIdx.x*256 + threadIdx.x;
    int row = idx / N, col = idx - row*N;
    float s = bias[col];
    const float* a = A + (size_t)row*K;
    for (int k = 0; k < K; k++) s = fmaf(a[k], W[(size_t)k*N + col], s);
    if (gelu) s = gelu_exact(s);
    if (Cf) Cf[idx] = s;
    if (Cb) Cb[idx] = __float2bfloat16(s);
}

// ---- flash v5: cp.async double-buffered K/V, mma.m16n8k16 bf16, QT=128, KC=64 ----
#define FQT 128
#define FKC 64
#define FQP 136
#define F4_KV 34816                      // Q tile bytes (128*136*2)
#define KVB_K 17408                      // 64*136*2
#define KVB   (2*KVB_K)                  // K+V per buffer
#define FLASH4_SMEM (F4_KV + 2*KVB)      // 104448

__global__ __launch_bounds__(256) void flash4(const __nv_bfloat16* __restrict__ qkv,
                                              __nv_bfloat16* __restrict__ out16) {
    __nv_bfloat16* Qs = (__nv_bfloat16*)dynsm;
    const int tid = threadIdx.x, wid = tid >> 5, lane = tid & 31;
    const int g = lane >> 2, tg = lane & 3;
    const int n0 = blockIdx.x*FQT, hh = blockIdx.y;
    const int t0 = n0 & (SEQ - 1), bb = n0 >> 11;
    const int wrow = wid*16;

    int jstart = t0 - (WINDOW - 1); if (jstart < 0) jstart = 0;
    const int tmax = t0 + FQT - 1;

    // K/V chunk loader lane mapping
    const int kvr = tid >> 2, kvc = (tid & 3)*32;
    const uint32_t kv0 = smem_u32(dynsm) + F4_KV;
    const uint32_t kvoff = (uint32_t)(kvr*FQP + kvc)*2;

    // prologue: cp.async chunk 0 into buffer 0 (overlaps Q load)
    {
        int ja = jstart + kvr; if (ja > tmax) ja = tmax;
        const __nv_bfloat16* kp = qkv + (size_t)((bb << 11) + ja)*1536 + HID + hh*DHEAD + kvc;
        uint32_t kd = kv0 + kvoff, vd = kd + KVB_K;
        #pragma unroll
        for (int q = 0; q < 4; q++) { cp16(kd + q*16, kp + q*8); cp16(vd + q*16, kp + HID + q*8); }
        CP_COMMIT();
    }
    // Q tile load
    {
        int r = tid >> 1, c0 = (tid & 1)*64;
        const __nv_bfloat16* qp = qkv + (size_t)(n0 + r)*1536 + hh*DHEAD + c0;
        __nv_bfloat16* qd = Qs + r*FQP + c0;
        #pragma unroll
        for (int q = 0; q < 8; q++) *(uint4*)(qd + q*8) = *(const uint4*)(qp + q*8);
    }
    __syncthreads();
    uint32_t aq[8][4];
    {
        int row = wrow + ((lane >> 3) & 1)*8 + (lane & 7);
        int colb = (lane >> 4)*8;
        #pragma unroll
        for (int s = 0; s < 8; s++)
            ldsm_x4(aq[s][0], aq[s][1], aq[s][2], aq[s][3],
                    smem_u32(Qs + row*FQP + s*16 + colb));
    }

    float o[16][4];
    #pragma unroll
    for (int f = 0; f < 16; f++) { o[f][0]=0; o[f][1]=0; o[f][2]=0; o[f][3]=0; }
    float m0 = -1e30f, m1 = -1e30f, l0 = 0.0f, l1 = 0.0f;
    const int tr0 = t0 + wrow + g, tr1 = tr0 + 8;

    int bufi = 0;
    for (int jc = jstart; jc <= tmax; jc += FKC, bufi ^= 1) {
        __syncthreads();      // prior compute done -> safe to overwrite buffer bufi^1
        if (jc + FKC <= tmax) {
            int ja = jc + FKC + kvr; if (ja > tmax) ja = tmax;
            const __nv_bfloat16* kp = qkv + (size_t)((bb << 11) + ja)*1536 + HID + hh*DHEAD + kvc;
            uint32_t kd = kv0 + (uint32_t)(bufi^1)*KVB + kvoff, vd = kd + KVB_K;
            #pragma unroll
            for (int q = 0; q < 4; q++) { cp16(kd + q*16, kp + q*8); cp16(vd + q*16, kp + HID + q*8); }
        }
        CP_COMMIT();
        CP_WAIT1();           // chunk jc landed (only the just-committed group may pend)
        __syncthreads();
        __nv_bfloat16* Ks = (__nv_bfloat16*)(dynsm + F4_KV + bufi*KVB);
        __nv_bfloat16* Vs = (__nv_bfloat16*)(dynsm + F4_KV + bufi*KVB + KVB_K);

        float sc[8][4];
        #pragma unroll
        for (int f = 0; f < 8; f++) { sc[f][0]=0; sc[f][1]=0; sc[f][2]=0; sc[f][3]=0; }
        {
            int krow_b = ((lane >> 4) & 1)*8 + (lane & 7);
            int kcol_b = ((lane >> 3) & 1)*8;
            #pragma unroll
            for (int ks = 0; ks < 8; ks++) {
                #pragma unroll
                for (int ng = 0; ng < 4; ng++) {
                    uint32_t r0, r1, r2, r3;
                    ldsm_x4(r0, r1, r2, r3,
                            smem_u32(Ks + (ng*16 + krow_b)*FQP + ks*16 + kcol_b));
                    mma16816(sc[2*ng],   aq[ks], r0, r1);
                    mma16816(sc[2*ng+1], aq[ks], r2, r3);
                }
            }
        }

        float r0max = -1e30f, r1max = -1e30f;
        #pragma unroll
        for (int f = 0; f < 8; f++) {
            int jb = jc + f*8 + tg*2;
            #pragma unroll
            for (int c = 0; c < 2; c++) {
                int ja = jb + c;
                bool ok0 = (ja <= tr0) && (ja > tr0 - WINDOW);
                bool ok1 = (ja <= tr1) && (ja > tr1 - WINDOW);
                sc[f][c]   = ok0 ? sc[f][c]*SM_SCALE   : -1e30f;
                sc[f][2+c] = ok1 ? sc[f][2+c]*SM_SCALE : -1e30f;
                r0max = fmaxf(r0max, sc[f][c]);
                r1max = fmaxf(r1max, sc[f][2+c]);
            }
        }
        r0max = fmaxf(r0max, __shfl_xor_sync(0xffffffffu, r0max, 1));
        r0max = fmaxf(r0max, __shfl_xor_sync(0xffffffffu, r0max, 2));
        r1max = fmaxf(r1max, __shfl_xor_sync(0xffffffffu, r1max, 1));
        r1max = fmaxf(r1max, __shfl_xor_sync(0xffffffffu, r1max, 2));
        float mc0 = fmaxf(m0, r0max), mc1 = fmaxf(m1, r1max);
        float ls0 = 0.0f, ls1 = 0.0f;
        #pragma unroll
        for (int f = 0; f < 8; f++) {
            #pragma unroll
            for (int c = 0; c < 2; c++) {
                float p0 = (sc[f][c]   <= -1e29f) ? 0.0f : __expf(sc[f][c]   - mc0);
                float p1 = (sc[f][2+c] <= -1e29f) ? 0.0f : __expf(sc[f][2+c] - mc1);
                sc[f][c] = p0; sc[f][2+c] = p1;
                ls0 += p0; ls1 += p1;
            }
        }
        ls0 += __shfl_xor_sync(0xffffffffu, ls0, 1);
        ls0 += __shfl_xor_sync(0xffffffffu, ls0, 2);
        ls1 += __shfl_xor_sync(0xffffffffu, ls1, 1);
        ls1 += __shfl_xor_sync(0xffffffffu, ls1, 2);
        float s0 = __expf(m0 - mc0), s1 = __expf(m1 - mc1);
        l0 = l0*s0 + ls0; l1 = l1*s1 + ls1;
        m0 = mc0; m1 = mc1;

        #pragma unroll
        for (int f = 0; f < 16; f++) {
            o[f][0] *= s0; o[f][1] *= s0; o[f][2] *= s1; o[f][3] *= s1;
        }
        uint32_t pa[4][4];
        #pragma unroll
        for (int s = 0; s < 4; s++) {
            pa[s][0] = packbf(sc[2*s][0],   sc[2*s][1]);
            pa[s][1] = packbf(sc[2*s][2],   sc[2*s][3]);
            pa[s][2] = packbf(sc[2*s+1][0], sc[2*s+1][1]);
            pa[s][3] = packbf(sc[2*s+1][2], sc[2*s+1][3]);
        }
        {
            int vrow_b = ((lane >> 3) & 1)*8 + (lane & 7);
            int vcol_b = (lane >> 4)*8;
            #pragma unroll
            for (int s = 0; s < 4; s++) {
                #pragma unroll
                for (int ng = 0; ng < 8; ng++) {
                    uint32_t r0, r1, r2, r3;
                    ldsm_x4_t(r0, r1, r2, r3,
                              smem_u32(Vs + (s*16 + vrow_b)*FQP + ng*16 + vcol_b));
                    mma16816(o[2*ng],   pa[s], r0, r1);
                    mma16816(o[2*ng+1], pa[s], r2, r3);
                }
            }
        }
    }

    float inv0 = 1.0f / l0, inv1 = 1.0f / l1;
    __nv_bfloat16* ob0 = out16 + (size_t)(n0 + wrow + g)*HID + hh*DHEAD + tg*2;
    __nv_bfloat16* ob1 = out16 + (size_t)(n0 + wrow + 8 + g)*HID + hh*DHEAD + tg*2;
    #pragma unroll
    for (int f = 0; f < 16; f++) {
        *(uint32_t*)(ob0 + f*8) = packbf(o[f][0]*inv0, o[f][1]*inv0);
        *(uint32_t*)(ob1 + f*8) = packbf(o[f][2]*inv1, o[f][3]*inv1);
    }
}

// ---- residual + LayerNorm: warp-per-token, no smem ----
__global__ __launch_bounds__(256) void ln_kernel(float* __restrict__ x,
                                                 const float* __restrict__ add,
                                                 const float* __restrict__ g,
                                                 const float* __restrict__ b,
                                                 __nv_bfloat16* __restrict__ x16) {
    const int lane = threadIdx.x & 31;
    const int n = blockIdx.x*8 + (threadIdx.x >> 5);
    const size_t base = (size_t)n*HID;
    float v[4][4];
    float s = 0.0f, sq = 0.0f;
    #pragma unroll
    for (int k = 0; k < 4; k++) {
        int c = k*128 + lane*4;
        float4 t = *(const float4*)(x + base + c);
        if (add) {
            float4 a = *(const float4*)(add + base + c);
            t.x += a.x; t.y += a.y; t.z += a.z; t.w += a.w;
        }
        v[k][0]=t.x; v[k][1]=t.y; v[k][2]=t.z; v[k][3]=t.w;
        s  += t.x + t.y + t.z + t.w;
        sq += t.x*t.x + t.y*t.y + t.z*t.z + t.w*t.w;
    }
    #pragma unroll
    for (int o = 16; o > 0; o >>= 1) {
        s  += __shfl_xor_sync(0xffffffffu, s,  o);
        sq += __shfl_xor_sync(0xffffffffu, sq, o);
    }
    float mean = s * (1.0f/512.0f);
    float rstd = rsqrtf(sq * (1.0f/512.0f) - mean*mean + LN_EPS);
    #pragma unroll
    for (int k = 0; k < 4; k++) {
        int c = k*128 + lane*4;
        float4 gv = *(const float4*)(g + c);
        float4 bv = *(const float4*)(b + c);
        float o0 = (v[k][0] - mean)*rstd*gv.x + bv.x;
        float o1 = (v[k][1] - mean)*rstd*gv.y + bv.y;
        float o2 = (v[k][2] - mean)*rstd*gv.z + bv.z;
        float o3 = (v[k][3] - mean)*rstd*gv.w + bv.w;
        float4 of = {o0, o1, o2, o3};
        *(float4*)(x + base + c) = of;
        uint2 ob = {packbf(o0, o1), packbf(o2, o3)};
        *(uint2*)(x16 + base + c) = ob;
    }
}

// ---- loss ----
__global__ __launch_bounds__(1024) void loss_kernel(const float* __restrict__ yhat,
                                                    const float* __restrict__ y,
                                                    float* __restrict__ out) {
    float s = 0.0f;
    for (int e = threadIdx.x; e < NTOK*8; e += 1024) {
        int n = e >> 3, d = e & 7;
        int b = n >> 11, t = n & (SEQ - 1);
        float diff = yhat[e] - y[(size_t)(b*8 + d)*SEQ + t];
        s = fmaf(diff, diff, s);
    }
    #pragma unroll
    for (int o = 16; o > 0; o >>= 1) s += __shfl_xor_sync(0xffffffffu, s, o);
    __shared__ float red[32];
    int w = threadIdx.x >> 5;
    if ((threadIdx.x & 31) == 0) red[w] = s;
    __syncthreads();
    if (threadIdx.x == 0) {
        float tot = 0;
        #pragma unroll
        for (int i = 0; i < 32; i++) tot += red[i];
        out[0] = tot;
    }
}

// ---- host ----
static inline void run_wm(const __nv_bfloat16* A, const __nv_bfloat16* B, const float* bias,
                          float* C32, __nv_bfloat16* C16, int N, int K, int gelu) {
    gemm_bf16<<<dim3(N/128, NTOK/128), 256, GEMM_SMEM>>>(A, B, bias, C32, C16, N, K, gelu);
}

extern "C" void kernel_launch(void* const* d_in, const int* in_sizes, int n_in,
                              void* d_out, int out_size) {
    const float *u = (const float*)d_in[0], *y = (const float*)d_in[1];
    const float *W_in = (const float*)d_in[2], *b_in = (const float*)d_in[3];
    const float *qkv_w = (const float*)d_in[4], *qkv_b = (const float*)d_in[5];
    const float *out_w = (const float*)d_in[6], *out_b = (const float*)d_in[7];
    const float *ff1_w = (const float*)d_in[8], *ff1_b = (const float*)d_in[9];
    const float *ff2_w = (const float*)d_in[10], *ff2_b = (const float*)d_in[11];
    const float *ln1_g = (const float*)d_in[12], *ln1_b = (const float*)d_in[13];
    const float *ln2_g = (const float*)d_in[14], *ln2_b = (const float*)d_in[15];
    const float *lnf_g = (const float*)d_in[16], *lnf_b = (const float*)d_in[17];
    const float *xm1_w = (const float*)d_in[18], *xm1_b = (const float*)d_in[19];
    const float *xm2_w = (const float*)d_in[20], *xm2_b = (const float*)d_in[21];
    const float *me1_w = (const float*)d_in[22], *me1_b = (const float*)d_in[23];
    const float *me2_w = (const float*)d_in[24], *me2_b = (const float*)d_in[25];
    const float *me3_w = (const float*)d_in[26], *me3_b = (const float*)d_in[27];

    static float *px = nullptr, *pf32, *pt2, *psmall, *pyhat;
    static __nv_bfloat16 *pqkv16, *px16, *pattn16, *pmid16, *pwt;
    if (!px) {
        cudaGetSymbolAddress((void**)&px, g_x);
        cudaGetSymbolAddress((void**)&pf32, g_f32);
        cudaGetSymbolAddress((void**)&pt2, g_t2);
        cudaGetSymbolAddress((void**)&psmall, g_small);
        cudaGetSymbolAddress((void**)&pyhat, g_yhat);
        cudaGetSymbolAddress((void**)&pqkv16, g_qkv16);
        cudaGetSymbolAddress((void**)&px16, g_x16);
        cudaGetSymbolAddress((void**)&pattn16, g_attn16);
        cudaGetSymbolAddress((void**)&pmid16, g_mid16);
        cudaGetSymbolAddress((void**)&pwt, g_wt);
        cudaFuncSetAttribute(flash4, cudaFuncAttributeMaxDynamicSharedMemorySize, FLASH4_SMEM);
        cudaFuncSetAttribute(gemm_bf16, cudaFuncAttributeMaxDynamicSharedMemorySize, GEMM_SMEM);
    }

    dim3 tb(32, 8);
    // launch order: #4 = QKV gemm_bf16; #5 = flash4 (ncu captures #4)
    wtrans<<<dim3(16, 48, 4), tb>>>(qkv_w, pwt + OFF_QKV, 512, 1536);   // 1
    wtrans<<<dim3(16, 16, 4), tb>>>(out_w, pwt + OFF_OUT, 512, 512);    // 2
    embed_kernel<<<NTOK, HID>>>(u, y, W_in, b_in, px, px16);            // 3

    for (int l = 0; l < NLAYER; l++) {
        run_wm(px16, pwt + OFF_QKV + (size_t)l*1536*512, qkv_b + l*1536, nullptr, pqkv16, 1536, 512, 0);  // 4
        flash4<<<dim3(NTOK/FQT, NHEAD), 256, FLASH4_SMEM>>>(pqkv16, pattn16);                             // 5
        if (l == 0) {
            wtrans<<<dim3(16, 64, 4), tb>>>(ff1_w, pwt + OFF_FF1, 512, 2048);
            wtrans<<<dim3(64, 16, 4), tb>>>(ff2_w, pwt + OFF_FF2, 2048, 512);
        }
        run_wm(pattn16, pwt + OFF_OUT + (size_t)l*512*512, out_b + l*512, pt2, nullptr, 512, 512, 0);
        ln_kernel<<<NTOK/8, 256>>>(px, pt2, ln1_g + l*HID, ln1_b + l*HID, px16);
        run_wm(px16, pwt + OFF_FF1 + (size_t)l*512*2048, ff1_b + l*2048, nullptr, pmid16, 2048, 512, 1);
        run_wm(pmid16, pwt + OFF_FF2 + (size_t)l*2048*512, ff2_b + l*512, pt2, nullptr, 512, 2048, 0);
        ln_kernel<<<NTOK/8, 256>>>(px, pt2, ln2_g + l*HID, ln2_b + l*HID, px16);
    }
    ln_kernel<<<NTOK/8, 256>>>(px, nullptr, lnf_g, lnf_b, px16);

    wtrans<<<dim3(16, 16, 1), tb>>>(xm1_w, pwt + OFF_XM1, 512, 512);
    wtrans<<<dim3(16, 16, 1), tb>>>(me2_w, pwt + OFF_ME2, 512, 512);
    run_wm(px16, pwt + OFF_XM1, xm1_b, pt2, nullptr, 512, 512, 1);
    gemm_naive<<<NTOK*16/256, 256>>>(pt2, xm2_w, xm2_b, psmall, nullptr, 16, 512, 0);
    gemm_naive<<<NTOK*512/256, 256>>>(psmall, me1_w, me1_b, nullptr, pattn16, 512, 16, 1);
    run_wm(pattn16, pwt + OFF_ME2, me2_b, pf32, nullptr, 512, 512, 1);
    gemm_naive<<<NTOK*8/256, 256>>>(pf32, me3_w, me3_b, pyhat, nullptr, 8, 512, 0);

    loss_kernel<<<1, 1024>>>(pyhat, y, (float*)d_out);
}

// round 16
// speedup vs baseline: 1.1797x; 1.0516x over previous
#include <cuda_runtime.h>
#include <cuda_bf16.h>
#include <math.h>
#include <stdint.h>

#define BATCH 4
#define SEQ   2048
#define HID   512
#define DFF   2048
#define NLAYER 4
#define NHEAD 4
#define DHEAD 128
#define WINDOW 606
#define KTRUE 30
#define NTOK  (BATCH*SEQ)
#define LN_EPS 1e-5f
#define SM_SCALE 0.08838834764831845f

// ---- scratch ----
__device__ float g_x[NTOK*HID];
__device__ float g_f32[NTOK*3*HID];
__device__ float g_t2[NTOK*HID];
__device__ float g_small[NTOK*16];
__device__ float g_yhat[NTOK*8];
__device__ __nv_bfloat16 g_qkv16[NTOK*3*HID];
__device__ __nv_bfloat16 g_x16[NTOK*HID];
__device__ __nv_bfloat16 g_attn16[NTOK*HID];
__device__ __nv_bfloat16 g_mid16[NTOK*DFF];
#define OFF_QKV 0
#define OFF_OUT (OFF_QKV + 4*1536*512)
#define OFF_FF1 (OFF_OUT + 4*512*512)
#define OFF_FF2 (OFF_FF1 + 4*2048*512)
#define OFF_XM1 (OFF_FF2 + 4*512*2048)
#define OFF_ME2 (OFF_XM1 + 512*512)
#define WT_TOTAL (OFF_ME2 + 512*512)
__device__ __nv_bfloat16 g_wt[WT_TOTAL];

__device__ __forceinline__ float gelu_exact(float v) {
    return 0.5f * v * (1.0f + erff(v * 0.7071067811865475f));
}
__device__ __forceinline__ uint32_t smem_u32(const void* p) {
    uint32_t a;
    asm("{ .reg .u64 t; cvta.to.shared.u64 t, %1; cvt.u32.u64 %0, t; }" : "=r"(a) : "l"(p));
    return a;
}
__device__ __forceinline__ void cp16(uint32_t d, const void* s) {
    asm volatile("cp.async.cg.shared.global [%0], [%1], 16;" :: "r"(d), "l"(s));
}
#define CP_COMMIT() asm volatile("cp.async.commit_group;" ::: "memory")
#define CP_WAIT1()  asm volatile("cp.async.wait_group 1;" ::: "memory")
#define CP_WAIT3()  asm volatile("cp.async.wait_group 3;" ::: "memory")

__device__ __forceinline__ void ldsm_x4(uint32_t& r0, uint32_t& r1, uint32_t& r2, uint32_t& r3,
                                        uint32_t addr) {
    asm volatile("ldmatrix.sync.aligned.m8n8.x4.shared.b16 {%0,%1,%2,%3}, [%4];"
        : "=r"(r0), "=r"(r1), "=r"(r2), "=r"(r3) : "r"(addr));
}
__device__ __forceinline__ void ldsm_x4_t(uint32_t& r0, uint32_t& r1, uint32_t& r2, uint32_t& r3,
                                          uint32_t addr) {
    asm volatile("ldmatrix.sync.aligned.m8n8.x4.trans.shared.b16 {%0,%1,%2,%3}, [%4];"
        : "=r"(r0), "=r"(r1), "=r"(r2), "=r"(r3) : "r"(addr));
}
__device__ __forceinline__ void mma16816(float* d, const uint32_t* a, uint32_t b0, uint32_t b1) {
    asm volatile("mma.sync.aligned.m16n8k16.row.col.f32.bf16.bf16.f32 "
        "{%0,%1,%2,%3}, {%4,%5,%6,%7}, {%8,%9}, {%0,%1,%2,%3};"
        : "+f"(d[0]), "+f"(d[1]), "+f"(d[2]), "+f"(d[3])
        : "r"(a[0]), "r"(a[1]), "r"(a[2]), "r"(a[3]), "r"(b0), "r"(b1));
}
__device__ __forceinline__ uint32_t packbf(float lo, float hi) {
    uint32_t d;
    asm("cvt.rn.bf16x2.f32 %0, %1, %2;" : "=r"(d) : "f"(hi), "f"(lo));
    return d;
}

extern __shared__ char dynsm[];

// ---- weight transpose: Wt[n][k] = bf16(W[k][n]) ----
__global__ void wtrans(const float* __restrict__ W, __nv_bfloat16* __restrict__ Wt, int K, int N) {
    __shared__ float t[32][33];
    size_t ws = (size_t)K*N;
    const float* Wl = W + blockIdx.z*ws;
    __nv_bfloat16* Wtl = Wt + blockIdx.z*ws;
    int k0 = blockIdx.x*32, n0 = blockIdx.y*32;
    for (int i = threadIdx.y; i < 32; i += 8)
        t[i][threadIdx.x] = Wl[(size_t)(k0+i)*N + n0 + threadIdx.x];
    __syncthreads();
    for (int i = threadIdx.y; i < 32; i += 8)
        Wtl[(size_t)(n0+i)*K + k0 + threadIdx.x] = __float2bfloat16(t[threadIdx.x][i]);
}

// ---- embed (dual write) ----
__global__ void embed_kernel(const float* __restrict__ u, const float* __restrict__ y,
                             const float* __restrict__ W_in, const float* __restrict__ b_in,
                             float* __restrict__ x, __nv_bfloat16* __restrict__ x16) {
    int n = blockIdx.x, c = threadIdx.x;
    int b = n >> 11, t = n & (SEQ - 1);
    __shared__ float ua[24];
    if (c < 8)       ua[c] = u[(size_t)(b*8 + c)*SEQ + t];
    else if (c < 16) ua[c] = 0.0f;
    else if (c < 24) ua[c] = (t < KTRUE) ? y[(size_t)(b*8 + (c-16))*SEQ + t] : 0.0f;
    __syncthreads();
    float s = b_in[c];
    #pragma unroll
    for (int k = 0; k < 24; k++) s = fmaf(ua[k], W_in[k*HID + c], s);
    float div = __expf(-9.210340371976184f * (float)(c & ~1) / (float)HID);
    float ang = (float)t * div;
    s += (c & 1) ? cosf(ang) : sinf(ang);
    x[(size_t)n*HID + c] = s;
    x16[(size_t)n*HID + c] = __float2bfloat16(s);
}

// ---- bf16 mma GEMM, 5-stage ring, prefetch distance 3, barrier every 2 chunks ----
// Chunk c lives in stage c%5; iteration ch prefetches chunk ch+3 into stage (ch+3)%5.
#define TK 32
#define WLD 40
#define STG_AB (128*WLD*2)
#define STG_B  (2*STG_AB)
#define NSTG 5
#define GEMM_SMEM (NSTG*STG_B)           // 102400
__global__ __launch_bounds__(256, 2) void gemm_bf16(
    const __nv_bfloat16* __restrict__ A, const __nv_bfloat16* __restrict__ B,
    const float* __restrict__ bias, float* __restrict__ C32,
    __nv_bfloat16* __restrict__ C16, int N, int K, int gelu) {
    const int tid = threadIdx.x;
    const int wid = tid >> 5, lane = tid & 31;
    const int wm = wid >> 1, wn = wid & 1;
    const int bm = blockIdx.y*128, bn = blockIdx.x*128;
    const uint32_t sbase = smem_u32(dynsm);

    float d[2][8][4];
    #pragma unroll
    for (int i = 0; i < 2; i++)
        #pragma unroll
        for (int j = 0; j < 8; j++) { d[i][j][0]=0; d[i][j][1]=0; d[i][j][2]=0; d[i][j][3]=0; }

    const int lr = tid >> 1, lc0 = (tid & 1)*16;
    const int nch = K / TK;
    const __nv_bfloat16* gA = A + (size_t)(bm+lr)*K + lc0;
    const __nv_bfloat16* gB = B + (size_t)(bn+lr)*K + lc0;
    const uint32_t soff = (uint32_t)(lr*WLD + lc0)*2;

    const int arow8 = ((lane >> 3) & 1)*8 + (lane & 7);
    const int acolb = (lane >> 4)*8;
    const int brow  = ((lane >> 4) & 1)*8 + (lane & 7);
    const int bcol  = ((lane >> 3) & 1)*8;

    // prologue: chunks 0..2 -> stages 0..2
    #pragma unroll
    for (int pc = 0; pc < 3; pc++) {
        uint32_t ua = sbase + pc*STG_B + soff;
        uint32_t ub = ua + STG_AB;
        const __nv_bfloat16* pa = gA + pc*TK;
        const __nv_bfloat16* pb = gB + pc*TK;
        cp16(ua, pa); cp16(ua + 16, pa + 8);
        cp16(ub, pb); cp16(ub + 16, pb + 8);
        CP_COMMIT();
    }
    int stg = 0;
    for (int ch = 0; ch < nch; ch++) {
        if ((ch & 1) == 0) __syncthreads();   // reuse distance 2 -> barrier every 2 chunks
        if (ch + 3 < nch) {
            int wstg = stg + 3; if (wstg >= NSTG) wstg -= NSTG;   // chunk ch+3 -> stage (ch+3)%5
            uint32_t ua = sbase + (uint32_t)wstg*STG_B + soff;
            uint32_t ub = ua + STG_AB;
            const __nv_bfloat16* pa = gA + (ch+3)*TK;
            const __nv_bfloat16* pb = gB + (ch+3)*TK;
            cp16(ua, pa); cp16(ua + 16, pa + 8);
            cp16(ub, pb); cp16(ub + 16, pb + 8);
        }
        CP_COMMIT();
        CP_WAIT3();           // committed = ch+4; <=3 pending => chunk ch landed
        const uint32_t Asb = sbase + (uint32_t)stg*STG_B;
        const uint32_t Bsb = Asb + STG_AB;
        #pragma unroll
        for (int ks = 0; ks < 2; ks++) {
            uint32_t a[2][4];
            #pragma unroll
            for (int mf = 0; mf < 2; mf++)
                ldsm_x4(a[mf][0], a[mf][1], a[mf][2], a[mf][3],
                        Asb + (uint32_t)((wm*32 + mf*16 + arow8)*WLD + ks*16 + acolb)*2);
            #pragma unroll
            for (int nf4 = 0; nf4 < 4; nf4++) {
                uint32_t r0, r1, r2, r3;
                ldsm_x4(r0, r1, r2, r3,
                        Bsb + (uint32_t)((wn*64 + nf4*16 + brow)*WLD + ks*16 + bcol)*2);
                mma16816(d[0][2*nf4],   a[0], r0, r1);
                mma16816(d[0][2*nf4+1], a[0], r2, r3);
                mma16816(d[1][2*nf4],   a[1], r0, r1);
                mma16816(d[1][2*nf4+1], a[1], r2, r3);
            }
        }
        stg = (stg + 1 == NSTG) ? 0 : stg + 1;
    }
    const int g = lane >> 2, tg = lane & 3;
    #pragma unroll
    for (int mf = 0; mf < 2; mf++) {
        #pragma unroll
        for (int half = 0; half < 2; half++) {
            int grow = bm + wm*32 + mf*16 + half*8 + g;
            #pragma unroll
            for (int nf = 0; nf < 8; nf++) {
                int gcol = bn + wn*64 + nf*8 + tg*2;
                float2 bv = *(const float2*)(bias + gcol);
                float v0 = d[mf][nf][half*2+0] + bv.x;
                float v1 = d[mf][nf][half*2+1] + bv.y;
                if (gelu) { v0 = gelu_exact(v0); v1 = gelu_exact(v1); }
                if (C32) {
                    float2 o = {v0, v1};
                    *(float2*)(C32 + (size_t)grow*N + gcol) = o;
                }
                if (C16) *(uint32_t*)(C16 + (size_t)grow*N + gcol) = packbf(v0, v1);
            }
        }
    }
}

// ---- naive fp32 gemm for tiny head shapes ----
__global__ void gemm_naive(const float* __restrict__ A, const float* __restrict__ W,
                           const float* __restrict__ bias, float* __restrict__ Cf,
                           __nv_bfloat16* __restrict__ Cb, int N, int K, int gelu) {
    int idx = blockIdx.x*256 + threadIdx.x;
    int row = idx / N, col = idx - row*N;
    float s = bias[col];
    const float* a = A + (size_t)row*K;
    for (int k = 0; k < K; k++) s = fmaf(a[k], W[(size_t)k*N + col], s);
    if (gelu) s = gelu_exact(s);
    if (Cf) Cf[idx] = s;
    if (Cb) Cb[idx] = __float2bfloat16(s);
}

// ---- flash v5: cp.async double-buffered K/V, interior fast path ----
#define FQT 128
#define FKC 64
#define FQP 136
#define F4_KV 34816
#define KVB_K 17408
#define KVB   (2*KVB_K)
#define FLASH4_SMEM (F4_KV + 2*KVB)      // 104448

__global__ __launch_bounds__(256) void flash4(const __nv_bfloat16* __restrict__ qkv,
                                              __nv_bfloat16* __restrict__ out16) {
    __nv_bfloat16* Qs = (__nv_bfloat16*)dynsm;
    const int tid = threadIdx.x, wid = tid >> 5, lane = tid & 31;
    const int g = lane >> 2, tg = lane & 3;
    const int n0 = blockIdx.x*FQT, hh = blockIdx.y;
    const int t0 = n0 & (SEQ - 1), bb = n0 >> 11;
    const int wrow = wid*16;

    int jstart = t0 - (WINDOW - 1); if (jstart < 0) jstart = 0;
    const int tmax = t0 + FQT - 1;

    const int kvr = tid >> 2, kvc = (tid & 3)*32;
    const uint32_t kv0 = smem_u32(dynsm) + F4_KV;
    const uint32_t kvoff = (uint32_t)(kvr*FQP + kvc)*2;

    {
        int ja = jstart + kvr; if (ja > tmax) ja = tmax;
        const __nv_bfloat16* kp = qkv + (size_t)((bb << 11) + ja)*1536 + HID + hh*DHEAD + kvc;
        uint32_t kd = kv0 + kvoff, vd = kd + KVB_K;
        #pragma unroll
        for (int q = 0; q < 4; q++) { cp16(kd + q*16, kp + q*8); cp16(vd + q*16, kp + HID + q*8); }
        CP_COMMIT();
    }
    {
        int r = tid >> 1, c0 = (tid & 1)*64;
        const __nv_bfloat16* qp = qkv + (size_t)(n0 + r)*1536 + hh*DHEAD + c0;
        __nv_bfloat16* qd = Qs + r*FQP + c0;
        #pragma unroll
        for (int q = 0; q < 8; q++) *(uint4*)(qd + q*8) = *(const uint4*)(qp + q*8);
    }
    __syncthreads();
    uint32_t aq[8][4];
    {
        int row = wrow + ((lane >> 3) & 1)*8 + (lane & 7);
        int colb = (lane >> 4)*8;
        #pragma unroll
        for (int s = 0; s < 8; s++)
            ldsm_x4(aq[s][0], aq[s][1], aq[s][2], aq[s][3],
                    smem_u32(Qs + row*FQP + s*16 + colb));
    }

    float o[16][4];
    #pragma unroll
    for (int f = 0; f < 16; f++) { o[f][0]=0; o[f][1]=0; o[f][2]=0; o[f][3]=0; }
    float m0 = -1e30f, m1 = -1e30f, l0 = 0.0f, l1 = 0.0f;
    const int tr0 = t0 + wrow + g, tr1 = tr0 + 8;

    int bufi = 0;
    for (int jc = jstart; jc <= tmax; jc += FKC, bufi ^= 1) {
        __syncthreads();
        if (jc + FKC <= tmax) {
            int ja = jc + FKC + kvr; if (ja > tmax) ja = tmax;
            const __nv_bfloat16* kp = qkv + (size_t)((bb << 11) + ja)*1536 + HID + hh*DHEAD + kvc;
            uint32_t kd = kv0 + (uint32_t)(bufi^1)*KVB + kvoff, vd = kd + KVB_K;
            #pragma unroll
            for (int q = 0; q < 4; q++) { cp16(kd + q*16, kp + q*8); cp16(vd + q*16, kp + HID + q*8); }
        }
        CP_COMMIT();
        CP_WAIT1();
        __syncthreads();
        __nv_bfloat16* Ks = (__nv_bfloat16*)(dynsm + F4_KV + bufi*KVB);
        __nv_bfloat16* Vs = (__nv_bfloat16*)(dynsm + F4_KV + bufi*KVB + KVB_K);

        float sc[8][4];
        #pragma unroll
        for (int f = 0; f < 8; f++) { sc[f][0]=0; sc[f][1]=0; sc[f][2]=0; sc[f][3]=0; }
        {
            int krow_b = ((lane >> 4) & 1)*8 + (lane & 7);
            int kcol_b = ((lane >> 3) & 1)*8;
            #pragma unroll
            for (int ks = 0; ks < 8; ks++) {
                #pragma unroll
                for (int ng = 0; ng < 4; ng++) {
                    uint32_t r0, r1, r2, r3;
                    ldsm_x4(r0, r1, r2, r3,
                            smem_u32(Ks + (ng*16 + krow_b)*FQP + ks*16 + kcol_b));
                    mma16816(sc[2*ng],   aq[ks], r0, r1);
                    mma16816(sc[2*ng+1], aq[ks], r2, r3);
                }
            }
        }

        const bool interior = (jc + FKC - 1 <= t0) && (jc + WINDOW > t0 + FQT - 1);
        float r0max = -1e30f, r1max = -1e30f;
        if (interior) {
            #pragma unroll
            for (int f = 0; f < 8; f++) {
                #pragma unroll
                for (int c = 0; c < 2; c++) {
                    sc[f][c]   *= SM_SCALE;
                    sc[f][2+c] *= SM_SCALE;
                    r0max = fmaxf(r0max, sc[f][c]);
                    r1max = fmaxf(r1max, sc[f][2+c]);
                }
            }
        } else {
            #pragma unroll
            for (int f = 0; f < 8; f++) {
                int jb = jc + f*8 + tg*2;
                #pragma unroll
                for (int c = 0; c < 2; c++) {
                    int ja = jb + c;
                    bool ok0 = (ja <= tr0) && (ja > tr0 - WINDOW);
                    bool ok1 = (ja <= tr1) && (ja > tr1 - WINDOW);
                    sc[f][c]   = ok0 ? sc[f][c]*SM_SCALE   : -1e30f;
                    sc[f][2+c] = ok1 ? sc[f][2+c]*SM_SCALE : -1e30f;
                    r0max = fmaxf(r0max, sc[f][c]);
                    r1max = fmaxf(r1max, sc[f][2+c]);
                }
            }
        }
        r0max = fmaxf(r0max, __shfl_xor_sync(0xffffffffu, r0max, 1));
        r0max = fmaxf(r0max, __shfl_xor_sync(0xffffffffu, r0max, 2));
        r1max = fmaxf(r1max, __shfl_xor_sync(0xffffffffu, r1max, 1));
        r1max = fmaxf(r1max, __shfl_xor_sync(0xffffffffu, r1max, 2));
        float mc0 = fmaxf(m0, r0max), mc1 = fmaxf(m1, r1max);
        float ls0 = 0.0f, ls1 = 0.0f;
        if (interior) {
            #pragma unroll
            for (int f = 0; f < 8; f++) {
                #pragma unroll
                for (int c = 0; c < 2; c++) {
                    float p0 = __expf(sc[f][c]   - mc0);
                    float p1 = __expf(sc[f][2+c] - mc1);
                    sc[f][c] = p0; sc[f][2+c] = p1;
                    ls0 += p0; ls1 += p1;
                }
            }
        } else {
            #pragma unroll
            for (int f = 0; f < 8; f++) {
                #pragma unroll
                for (int c = 0; c < 2; c++) {
                    float p0 = (sc[f][c]   <= -1e29f) ? 0.0f : __expf(sc[f][c]   - mc0);
                    float p1 = (sc[f][2+c] <= -1e29f) ? 0.0f : __expf(sc[f][2+c] - mc1);
                    sc[f][c] = p0; sc[f][2+c] = p1;
                    ls0 += p0; ls1 += p1;
                }
            }
        }
        ls0 += __shfl_xor_sync(0xffffffffu, ls0, 1);
        ls0 += __shfl_xor_sync(0xffffffffu, ls0, 2);
        ls1 += __shfl_xor_sync(0xffffffffu, ls1, 1);
        ls1 += __shfl_xor_sync(0xffffffffu, ls1, 2);
        float s0 = __expf(m0 - mc0), s1 = __expf(m1 - mc1);
        l0 = l0*s0 + ls0; l1 = l1*s1 + ls1;
        m0 = mc0; m1 = mc1;

        #pragma unroll
        for (int f = 0; f < 16; f++) {
            o[f][0] *= s0; o[f][1] *= s0; o[f][2] *= s1; o[f][3] *= s1;
        }
        uint32_t pa[4][4];
        #pragma unroll
        for (int s = 0; s < 4; s++) {
            pa[s][0] = packbf(sc[2*s][0],   sc[2*s][1]);
            pa[s][1] = packbf(sc[2*s][2],   sc[2*s][3]);
            pa[s][2] = packbf(sc[2*s+1][0], sc[2*s+1][1]);
            pa[s][3] = packbf(sc[2*s+1][2], sc[2*s+1][3]);
        }
        {
            int vrow_b = ((lane >> 3) & 1)*8 + (lane & 7);
            int vcol_b = (lane >> 4)*8;
            #pragma unroll
            for (int s = 0; s < 4; s++) {
                #pragma unroll
                for (int ng = 0; ng < 8; ng++) {
                    uint32_t r0, r1, r2, r3;
                    ldsm_x4_t(r0, r1, r2, r3,
                              smem_u32(Vs + (s*16 + vrow_b)*FQP + ng*16 + vcol_b));
                    mma16816(o[2*ng],   pa[s], r0, r1);
                    mma16816(o[2*ng+1], pa[s], r2, r3);
                }
            }
        }
    }

    float inv0 = 1.0f / l0, inv1 = 1.0f / l1;
    __nv_bfloat16* ob0 = out16 + (size_t)(n0 + wrow + g)*HID + hh*DHEAD + tg*2;
    __nv_bfloat16* ob1 = out16 + (size_t)(n0 + wrow + 8 + g)*HID + hh*DHEAD + tg*2;
    #pragma unroll
    for (int f = 0; f < 16; f++) {
        *(uint32_t*)(ob0 + f*8) = packbf(o[f][0]*inv0, o[f][1]*inv0);
        *(uint32_t*)(ob1 + f*8) = packbf(o[f][2]*inv1, o[f][3]*inv1);
    }
}

// ---- residual + LayerNorm: warp-per-token, no smem ----
__global__ __launch_bounds__(256) void ln_kernel(float* __restrict__ x,
                                                 const float* __restrict__ add,
                                                 const float* __restrict__ g,
                                                 const float* __restrict__ b,
                                                 __nv_bfloat16* __restrict__ x16) {
    const int lane = threadIdx.x & 31;
    const int n = blockIdx.x*8 + (threadIdx.x >> 5);
    const size_t base = (size_t)n*HID;
    float v[4][4];
    float s = 0.0f, sq = 0.0f;
    #pragma unroll
    for (int k = 0; k < 4; k++) {
        int c = k*128 + lane*4;
        float4 t = *(const float4*)(x + base + c);
        if (add) {
            float4 a = *(const float4*)(add + base + c);
            t.x += a.x; t.y += a.y; t.z += a.z; t.w += a.w;
        }
        v[k][0]=t.x; v[k][1]=t.y; v[k][2]=t.z; v[k][3]=t.w;
        s  += t.x + t.y + t.z + t.w;
        sq += t.x*t.x + t.y*t.y + t.z*t.z + t.w*t.w;
    }
    #pragma unroll
    for (int o = 16; o > 0; o >>= 1) {
        s  += __shfl_xor_sync(0xffffffffu, s,  o);
        sq += __shfl_xor_sync(0xffffffffu, sq, o);
    }
    float mean = s * (1.0f/512.0f);
    float rstd = rsqrtf(sq * (1.0f/512.0f) - mean*mean + LN_EPS);
    #pragma unroll
    for (int k = 0; k < 4; k++) {
        int c = k*128 + lane*4;
        float4 gv = *(const float4*)(g + c);
        float4 bv = *(const float4*)(b + c);
        float o0 = (v[k][0] - mean)*rstd*gv.x + bv.x;
        float o1 = (v[k][1] - mean)*rstd*gv.y + bv.y;
        float o2 = (v[k][2] - mean)*rstd*gv.z + bv.z;
        float o3 = (v[k][3] - mean)*rstd*gv.w + bv.w;
        float4 of = {o0, o1, o2, o3};
        *(float4*)(x + base + c) = of;
        uint2 ob = {packbf(o0, o1), packbf(o2, o3)};
        *(uint2*)(x16 + base + c) = ob;
    }
}

// ---- loss ----
__global__ __launch_bounds__(1024) void loss_kernel(const float* __restrict__ yhat,
                                                    const float* __restrict__ y,
                                                    float* __restrict__ out) {
    float s = 0.0f;
    for (int e = threadIdx.x; e < NTOK*8; e += 1024) {
        int n = e >> 3, d = e & 7;
        int b = n >> 11, t = n & (SEQ - 1);
        float diff = yhat[e] - y[(size_t)(b*8 + d)*SEQ + t];
        s = fmaf(diff, diff, s);
    }
    #pragma unroll
    for (int o = 16; o > 0; o >>= 1) s += __shfl_xor_sync(0xffffffffu, s, o);
    __shared__ float red[32];
    int w = threadIdx.x >> 5;
    if ((threadIdx.x & 31) == 0) red[w] = s;
    __syncthreads();
    if (threadIdx.x == 0) {
        float tot = 0;
        #pragma unroll
        for (int i = 0; i < 32; i++) tot += red[i];
        out[0] = tot;
    }
}

// ---- host ----
static inline void run_wm(const __nv_bfloat16* A, const __nv_bfloat16* B, const float* bias,
                          float* C32, __nv_bfloat16* C16, int N, int K, int gelu) {
    gemm_bf16<<<dim3(N/128, NTOK/128), 256, GEMM_SMEM>>>(A, B, bias, C32, C16, N, K, gelu);
}

extern "C" void kernel_launch(void* const* d_in, const int* in_sizes, int n_in,
                              void* d_out, int out_size) {
    const float *u = (const float*)d_in[0], *y = (const float*)d_in[1];
    const float *W_in = (const float*)d_in[2], *b_in = (const float*)d_in[3];
    const float *qkv_w = (const float*)d_in[4], *qkv_b = (const float*)d_in[5];
    const float *out_w = (const float*)d_in[6], *out_b = (const float*)d_in[7];
    const float *ff1_w = (const float*)d_in[8], *ff1_b = (const float*)d_in[9];
    const float *ff2_w = (const float*)d_in[10], *ff2_b = (const float*)d_in[11];
    const float *ln1_g = (const float*)d_in[12], *ln1_b = (const float*)d_in[13];
    const float *ln2_g = (const float*)d_in[14], *ln2_b = (const float*)d_in[15];
    const float *lnf_g = (const float*)d_in[16], *lnf_b = (const float*)d_in[17];
    const float *xm1_w = (const float*)d_in[18], *xm1_b = (const float*)d_in[19];
    const float *xm2_w = (const float*)d_in[20], *xm2_b = (const float*)d_in[21];
    const float *me1_w = (const float*)d_in[22], *me1_b = (const float*)d_in[23];
    const float *me2_w = (const float*)d_in[24], *me2_b = (const float*)d_in[25];
    const float *me3_w = (const float*)d_in[26], *me3_b = (const float*)d_in[27];

    static float *px = nullptr, *pf32, *pt2, *psmall, *pyhat;
    static __nv_bfloat16 *pqkv16, *px16, *pattn16, *pmid16, *pwt;
    if (!px) {
        cudaGetSymbolAddress((void**)&px, g_x);
        cudaGetSymbolAddress((void**)&pf32, g_f32);
        cudaGetSymbolAddress((void**)&pt2, g_t2);
        cudaGetSymbolAddress((void**)&psmall, g_small);
        cudaGetSymbolAddress((void**)&pyhat, g_yhat);
        cudaGetSymbolAddress((void**)&pqkv16, g_qkv16);
        cudaGetSymbolAddress((void**)&px16, g_x16);
        cudaGetSymbolAddress((void**)&pattn16, g_attn16);
        cudaGetSymbolAddress((void**)&pmid16, g_mid16);
        cudaGetSymbolAddress((void**)&pwt, g_wt);
        cudaFuncSetAttribute(flash4, cudaFuncAttributeMaxDynamicSharedMemorySize, FLASH4_SMEM);
        cudaFuncSetAttribute(gemm_bf16, cudaFuncAttributeMaxDynamicSharedMemorySize, GEMM_SMEM);
    }

    dim3 tb(32, 8);
    // launch order: #4 = flash4 (ncu captures process-launch #4)
    wtrans<<<dim3(16, 48, 4), tb>>>(qkv_w, pwt + OFF_QKV, 512, 1536);   // 1
    embed_kernel<<<NTOK, HID>>>(u, y, W_in, b_in, px, px16);            // 2

    for (int l = 0; l < NLAYER; l++) {
        run_wm(px16, pwt + OFF_QKV + (size_t)l*1536*512, qkv_b + l*1536, nullptr, pqkv16, 1536, 512, 0);  // 3
        flash4<<<dim3(NTOK/FQT, NHEAD), 256, FLASH4_SMEM>>>(pqkv16, pattn16);                             // 4
        if (l == 0) {
            wtrans<<<dim3(16, 16, 4), tb>>>(out_w, pwt + OFF_OUT, 512, 512);
            wtrans<<<dim3(16, 64, 4), tb>>>(ff1_w, pwt + OFF_FF1, 512, 2048);
            wtrans<<<dim3(64, 16, 4), tb>>>(ff2_w, pwt + OFF_FF2, 2048, 512);
        }
        run_wm(pattn16, pwt + OFF_OUT + (size_t)l*512*512, out_b + l*512, pt2, nullptr, 512, 512, 0);
        ln_kernel<<<NTOK/8, 256>>>(px, pt2, ln1_g + l*HID, ln1_b + l*HID, px16);
        run_wm(px16, pwt + OFF_FF1 + (size_t)l*512*2048, ff1_b + l*2048, nullptr, pmid16, 2048, 512, 1);
        run_wm(pmid16, pwt + OFF_FF2 + (size_t)l*2048*512, ff2_b + l*512, pt2, nullptr, 512, 2048, 0);
        ln_kernel<<<NTOK/8, 256>>>(px, pt2, ln2_g + l*HID, ln2_b + l*HID, px16);
    }
    ln_kernel<<<NTOK/8, 256>>>(px, nullptr, lnf_g, lnf_b, px16);

    wtrans<<<dim3(16, 16, 1), tb>>>(xm1_w, pwt + OFF_XM1, 512, 512);
    wtrans<<<dim3(16, 16, 1), tb>>>(me2_w, pwt + OFF_ME2, 512, 512);
    run_wm(px16, pwt + OFF_XM1, xm1_b, pt2, nullptr, 512, 512, 1);
    gemm_naive<<<NTOK*16/256, 256>>>(pt2, xm2_w, xm2_b, psmall, nullptr, 16, 512, 0);
    gemm_naive<<<NTOK*512/256, 256>>>(psmall, me1_w, me1_b, nullptr, pattn16, 512, 16, 1);
    run_wm(pattn16, pwt + OFF_ME2, me2_b, pf32, nullptr, 512, 512, 1);
    gemm_naive<<<NTOK*8/256, 256>>>(pf32, me3_w, me3_b, pyhat, nullptr, 8, 512, 0);

    loss_kernel<<<1, 1024>>>(pyhat, y, (float*)d_out);
}

// round 17
// speedup vs baseline: 1.1889x; 1.0078x over previous
#include <cuda_runtime.h>
#include <cuda_bf16.h>
#include <math.h>
#include <stdint.h>

#define BATCH 4
#define SEQ   2048
#define HID   512
#define DFF   2048
#define NLAYER 4
#define NHEAD 4
#define DHEAD 128
#define WINDOW 606
#define KTRUE 30
#define NTOK  (BATCH*SEQ)
#define LN_EPS 1e-5f
#define SM_SCALE 0.08838834764831845f

// ---- scratch ----
__device__ float g_x[NTOK*HID];
__device__ float g_f32[NTOK*3*HID];
__device__ float g_t2[NTOK*HID];
__device__ float g_small[NTOK*16];
__device__ float g_yhat[NTOK*8];
__device__ __nv_bfloat16 g_qkv16[NTOK*3*HID];
__device__ __nv_bfloat16 g_x16[NTOK*HID];
__device__ __nv_bfloat16 g_attn16[NTOK*HID];
__device__ __nv_bfloat16 g_mid16[NTOK*DFF];
#define OFF_QKV 0
#define OFF_OUT (OFF_QKV + 4*1536*512)
#define OFF_FF1 (OFF_OUT + 4*512*512)
#define OFF_FF2 (OFF_FF1 + 4*2048*512)
#define OFF_XM1 (OFF_FF2 + 4*512*2048)
#define OFF_ME2 (OFF_XM1 + 512*512)
#define WT_TOTAL (OFF_ME2 + 512*512)
__device__ __nv_bfloat16 g_wt[WT_TOTAL];

__device__ __forceinline__ float gelu_exact(float v) {
    return 0.5f * v * (1.0f + erff(v * 0.7071067811865475f));
}
__device__ __forceinline__ uint32_t smem_u32(const void* p) {
    uint32_t a;
    asm("{ .reg .u64 t; cvta.to.shared.u64 t, %1; cvt.u32.u64 %0, t; }" : "=r"(a) : "l"(p));
    return a;
}
__device__ __forceinline__ void cp16(uint32_t d, const void* s) {
    asm volatile("cp.async.cg.shared.global [%0], [%1], 16;" :: "r"(d), "l"(s));
}
#define CP_COMMIT() asm volatile("cp.async.commit_group;" ::: "memory")
#define CP_WAIT2()  asm volatile("cp.async.wait_group 2;" ::: "memory")
#define CP_WAIT3()  asm volatile("cp.async.wait_group 3;" ::: "memory")

__device__ __forceinline__ void ldsm_x4(uint32_t& r0, uint32_t& r1, uint32_t& r2, uint32_t& r3,
                                        uint32_t addr) {
    asm volatile("ldmatrix.sync.aligned.m8n8.x4.shared.b16 {%0,%1,%2,%3}, [%4];"
        : "=r"(r0), "=r"(r1), "=r"(r2), "=r"(r3) : "r"(addr));
}
__device__ __forceinline__ void ldsm_x4_t(uint32_t& r0, uint32_t& r1, uint32_t& r2, uint32_t& r3,
                                          uint32_t addr) {
    asm volatile("ldmatrix.sync.aligned.m8n8.x4.trans.shared.b16 {%0,%1,%2,%3}, [%4];"
        : "=r"(r0), "=r"(r1), "=r"(r2), "=r"(r3) : "r"(addr));
}
__device__ __forceinline__ void mma16816(float* d, const uint32_t* a, uint32_t b0, uint32_t b1) {
    asm volatile("mma.sync.aligned.m16n8k16.row.col.f32.bf16.bf16.f32 "
        "{%0,%1,%2,%3}, {%4,%5,%6,%7}, {%8,%9}, {%0,%1,%2,%3};"
        : "+f"(d[0]), "+f"(d[1]), "+f"(d[2]), "+f"(d[3])
        : "r"(a[0]), "r"(a[1]), "r"(a[2]), "r"(a[3]), "r"(b0), "r"(b1));
}
__device__ __forceinline__ uint32_t packbf(float lo, float hi) {
    uint32_t d;
    asm("cvt.rn.bf16x2.f32 %0, %1, %2;" : "=r"(d) : "f"(hi), "f"(lo));
    return d;
}

extern __shared__ char dynsm[];

// ---- weight transpose: Wt[n][k] = bf16(W[k][n]) ----
__global__ void wtrans(const float* __restrict__ W, __nv_bfloat16* __restrict__ Wt, int K, int N) {
    __shared__ float t[32][33];
    size_t ws = (size_t)K*N;
    const float* Wl = W + blockIdx.z*ws;
    __nv_bfloat16* Wtl = Wt + blockIdx.z*ws;
    int k0 = blockIdx.x*32, n0 = blockIdx.y*32;
    for (int i = threadIdx.y; i < 32; i += 8)
        t[i][threadIdx.x] = Wl[(size_t)(k0+i)*N + n0 + threadIdx.x];
    __syncthreads();
    for (int i = threadIdx.y; i < 32; i += 8)
        Wtl[(size_t)(n0+i)*K + k0 + threadIdx.x] = __float2bfloat16(t[threadIdx.x][i]);
}

// ---- embed (dual write) ----
__global__ void embed_kernel(const float* __restrict__ u, const float* __restrict__ y,
                             const float* __restrict__ W_in, const float* __restrict__ b_in,
                             float* __restrict__ x, __nv_bfloat16* __restrict__ x16) {
    int n = blockIdx.x, c = threadIdx.x;
    int b = n >> 11, t = n & (SEQ - 1);
    __shared__ float ua[24];
    if (c < 8)       ua[c] = u[(size_t)(b*8 + c)*SEQ + t];
    else if (c < 16) ua[c] = 0.0f;
    else if (c < 24) ua[c] = (t < KTRUE) ? y[(size_t)(b*8 + (c-16))*SEQ + t] : 0.0f;
    __syncthreads();
    float s = b_in[c];
    #pragma unroll
    for (int k = 0; k < 24; k++) s = fmaf(ua[k], W_in[k*HID + c], s);
    float div = __expf(-9.210340371976184f * (float)(c & ~1) / (float)HID);
    float ang = (float)t * div;
    s += (c & 1) ? cosf(ang) : sinf(ang);
    x[(size_t)n*HID + c] = s;
    x16[(size_t)n*HID + c] = __float2bfloat16(s);
}

// ---- bf16 mma GEMM (R16, frozen): 5-stage ring, distance 3, barrier every 2 chunks ----
#define TK 32
#define WLD 40
#define STG_AB (128*WLD*2)
#define STG_B  (2*STG_AB)
#define NSTG 5
#define GEMM_SMEM (NSTG*STG_B)
__global__ __launch_bounds__(256, 2) void gemm_bf16(
    const __nv_bfloat16* __restrict__ A, const __nv_bfloat16* __restrict__ B,
    const float* __restrict__ bias, float* __restrict__ C32,
    __nv_bfloat16* __restrict__ C16, int N, int K, int gelu) {
    const int tid = threadIdx.x;
    const int wid = tid >> 5, lane = tid & 31;
    const int wm = wid >> 1, wn = wid & 1;
    const int bm = blockIdx.y*128, bn = blockIdx.x*128;
    const uint32_t sbase = smem_u32(dynsm);

    float d[2][8][4];
    #pragma unroll
    for (int i = 0; i < 2; i++)
        #pragma unroll
        for (int j = 0; j < 8; j++) { d[i][j][0]=0; d[i][j][1]=0; d[i][j][2]=0; d[i][j][3]=0; }

    const int lr = tid >> 1, lc0 = (tid & 1)*16;
    const int nch = K / TK;
    const __nv_bfloat16* gA = A + (size_t)(bm+lr)*K + lc0;
    const __nv_bfloat16* gB = B + (size_t)(bn+lr)*K + lc0;
    const uint32_t soff = (uint32_t)(lr*WLD + lc0)*2;

    const int arow8 = ((lane >> 3) & 1)*8 + (lane & 7);
    const int acolb = (lane >> 4)*8;
    const int brow  = ((lane >> 4) & 1)*8 + (lane & 7);
    const int bcol  = ((lane >> 3) & 1)*8;

    #pragma unroll
    for (int pc = 0; pc < 3; pc++) {
        uint32_t ua = sbase + pc*STG_B + soff;
        uint32_t ub = ua + STG_AB;
        const __nv_bfloat16* pa = gA + pc*TK;
        const __nv_bfloat16* pb = gB + pc*TK;
        cp16(ua, pa); cp16(ua + 16, pa + 8);
        cp16(ub, pb); cp16(ub + 16, pb + 8);
        CP_COMMIT();
    }
    int stg = 0;
    for (int ch = 0; ch < nch; ch++) {
        if ((ch & 1) == 0) __syncthreads();
        if (ch + 3 < nch) {
            int wstg = stg + 3; if (wstg >= NSTG) wstg -= NSTG;
            uint32_t ua = sbase + (uint32_t)wstg*STG_B + soff;
            uint32_t ub = ua + STG_AB;
            const __nv_bfloat16* pa = gA + (ch+3)*TK;
            const __nv_bfloat16* pb = gB + (ch+3)*TK;
            cp16(ua, pa); cp16(ua + 16, pa + 8);
            cp16(ub, pb); cp16(ub + 16, pb + 8);
        }
        CP_COMMIT();
        CP_WAIT3();
        const uint32_t Asb = sbase + (uint32_t)stg*STG_B;
        const uint32_t Bsb = Asb + STG_AB;
        #pragma unroll
        for (int ks = 0; ks < 2; ks++) {
            uint32_t a[2][4];
            #pragma unroll
            for (int mf = 0; mf < 2; mf++)
                ldsm_x4(a[mf][0], a[mf][1], a[mf][2], a[mf][3],
                        Asb + (uint32_t)((wm*32 + mf*16 + arow8)*WLD + ks*16 + acolb)*2);
            #pragma unroll
            for (int nf4 = 0; nf4 < 4; nf4++) {
                uint32_t r0, r1, r2, r3;
                ldsm_x4(r0, r1, r2, r3,
                        Bsb + (uint32_t)((wn*64 + nf4*16 + brow)*WLD + ks*16 + bcol)*2);
                mma16816(d[0][2*nf4],   a[0], r0, r1);
                mma16816(d[0][2*nf4+1], a[0], r2, r3);
                mma16816(d[1][2*nf4],   a[1], r0, r1);
                mma16816(d[1][2*nf4+1], a[1], r2, r3);
            }
        }
        stg = (stg + 1 == NSTG) ? 0 : stg + 1;
    }
    const int g = lane >> 2, tg = lane & 3;
    #pragma unroll
    for (int mf = 0; mf < 2; mf++) {
        #pragma unroll
        for (int half = 0; half < 2; half++) {
            int grow = bm + wm*32 + mf*16 + half*8 + g;
            #pragma unroll
            for (int nf = 0; nf < 8; nf++) {
                int gcol = bn + wn*64 + nf*8 + tg*2;
                float2 bv = *(const float2*)(bias + gcol);
                float v0 = d[mf][nf][half*2+0] + bv.x;
                float v1 = d[mf][nf][half*2+1] + bv.y;
                if (gelu) { v0 = gelu_exact(v0); v1 = gelu_exact(v1); }
                if (C32) {
                    float2 o = {v0, v1};
                    *(float2*)(C32 + (size_t)grow*N + gcol) = o;
                }
                if (C16) *(uint32_t*)(C16 + (size_t)grow*N + gcol) = packbf(v0, v1);
            }
        }
    }
}

// ---- naive gemm for tiny head shapes (float4 A loads) ----
__global__ void gemm_naive(const float* __restrict__ A, const float* __restrict__ W,
                           const float* __restrict__ bias, float* __restrict__ Cf,
                           __nv_bfloat16* __restrict__ Cb, int N, int K, int gelu) {
    int idx = blockIdx.x*256 + threadIdx.x;
    int row = idx / N, col = idx - row*N;
    float s = bias[col];
    const float4* a4 = (const float4*)(A + (size_t)row*K);
    const float* wc = W + col;
    #pragma unroll 4
    for (int k4 = 0; k4 < K/4; k4++) {
        float4 av = a4[k4];
        int kb = k4*4;
        s = fmaf(av.x, wc[(size_t)kb*N], s);
        s = fmaf(av.y, wc[(size_t)(kb+1)*N], s);
        s = fmaf(av.z, wc[(size_t)(kb+2)*N], s);
        s = fmaf(av.w, wc[(size_t)(kb+3)*N], s);
    }
    if (gelu) s = gelu_exact(s);
    if (Cf) Cf[idx] = s;
    if (Cb) Cb[idx] = __float2bfloat16(s);
}

// ---- flash v6: 4 K/V buffers, distance-2 prefetch, ONE sync per chunk ----
#define FQT 128
#define FKC 64
#define FQP 136
#define F4_KV 34816
#define KVB_K 17408
#define KVB   (2*KVB_K)
#define FLASH4_SMEM (F4_KV + 4*KVB)      // 174080

__global__ __launch_bounds__(256) void flash4(const __nv_bfloat16* __restrict__ qkv,
                                              __nv_bfloat16* __restrict__ out16) {
    __nv_bfloat16* Qs = (__nv_bfloat16*)dynsm;
    const int tid = threadIdx.x, wid = tid >> 5, lane = tid & 31;
    const int g = lane >> 2, tg = lane & 3;
    const int n0 = blockIdx.x*FQT, hh = blockIdx.y;
    const int t0 = n0 & (SEQ - 1), bb = n0 >> 11;
    const int wrow = wid*16;

    int jstart = t0 - (WINDOW - 1); if (jstart < 0) jstart = 0;
    const int tmax = t0 + FQT - 1;

    const int kvr = tid >> 2, kvc = (tid & 3)*32;
    const uint32_t kv0 = smem_u32(dynsm) + F4_KV;
    const uint32_t kvoff = (uint32_t)(kvr*FQP + kvc)*2;

    // prologue: chunks 0,1 -> buffers 0,1 (one group each)
    #pragma unroll
    for (int pc = 0; pc < 2; pc++) {
        int ja = jstart + pc*FKC + kvr; if (ja > tmax) ja = tmax;
        const __nv_bfloat16* kp = qkv + (size_t)((bb << 11) + ja)*1536 + HID + hh*DHEAD + kvc;
        uint32_t kd = kv0 + (uint32_t)pc*KVB + kvoff, vd = kd + KVB_K;
        #pragma unroll
        for (int q = 0; q < 4; q++) { cp16(kd + q*16, kp + q*8); cp16(vd + q*16, kp + HID + q*8); }
        CP_COMMIT();
    }
    // Q tile load
    {
        int r = tid >> 1, c0 = (tid & 1)*64;
        const __nv_bfloat16* qp = qkv + (size_t)(n0 + r)*1536 + hh*DHEAD + c0;
        __nv_bfloat16* qd = Qs + r*FQP + c0;
        #pragma unroll
        for (int q = 0; q < 8; q++) *(uint4*)(qd + q*8) = *(const uint4*)(qp + q*8);
    }
    __syncthreads();
    uint32_t aq[8][4];
    {
        int row = wrow + ((lane >> 3) & 1)*8 + (lane & 7);
        int colb = (lane >> 4)*8;
        #pragma unroll
        for (int s = 0; s < 8; s++)
            ldsm_x4(aq[s][0], aq[s][1], aq[s][2], aq[s][3],
                    smem_u32(Qs + row*FQP + s*16 + colb));
    }

    float o[16][4];
    #pragma unroll
    for (int f = 0; f < 16; f++) { o[f][0]=0; o[f][1]=0; o[f][2]=0; o[f][3]=0; }
    float m0 = -1e30f, m1 = -1e30f, l0 = 0.0f, l1 = 0.0f;
    const int tr0 = t0 + wrow + g, tr1 = tr0 + 8;

    int bufi = 0;
    for (int jc = jstart; jc <= tmax; jc += FKC, bufi = (bufi + 1) & 3) {
        // prefetch chunk +2 into buffer (bufi+2)&3 (safe: != any buffer readable this region)
        if (jc + 2*FKC <= tmax) {
            int ja = jc + 2*FKC + kvr; if (ja > tmax) ja = tmax;
            const __nv_bfloat16* kp = qkv + (size_t)((bb << 11) + ja)*1536 + HID + hh*DHEAD + kvc;
            uint32_t kd = kv0 + (uint32_t)((bufi + 2) & 3)*KVB + kvoff, vd = kd + KVB_K;
            #pragma unroll
            for (int q = 0; q < 4; q++) { cp16(kd + q*16, kp + q*8); cp16(vd + q*16, kp + HID + q*8); }
        }
        CP_COMMIT();
        CP_WAIT2();           // chunk jc landed (own copies)
        __syncthreads();      // cross-thread visibility + compute ordering
        __nv_bfloat16* Ks = (__nv_bfloat16*)(dynsm + F4_KV + bufi*KVB);
        __nv_bfloat16* Vs = (__nv_bfloat16*)(dynsm + F4_KV + bufi*KVB + KVB_K);

        float sc[8][4];
        #pragma unroll
        for (int f = 0; f < 8; f++) { sc[f][0]=0; sc[f][1]=0; sc[f][2]=0; sc[f][3]=0; }
        {
            int krow_b = ((lane >> 4) & 1)*8 + (lane & 7);
            int kcol_b = ((lane >> 3) & 1)*8;
            #pragma unroll
            for (int ks = 0; ks < 8; ks++) {
                #pragma unroll
                for (int ng = 0; ng < 4; ng++) {
                    uint32_t r0, r1, r2, r3;
                    ldsm_x4(r0, r1, r2, r3,
                            smem_u32(Ks + (ng*16 + krow_b)*FQP + ks*16 + kcol_b));
                    mma16816(sc[2*ng],   aq[ks], r0, r1);
                    mma16816(sc[2*ng+1], aq[ks], r2, r3);
                }
            }
        }

        const bool interior = (jc + FKC - 1 <= t0) && (jc + WINDOW > t0 + FQT - 1);
        float r0max = -1e30f, r1max = -1e30f;
        if (interior) {
            #pragma unroll
            for (int f = 0; f < 8; f++) {
                #pragma unroll
                for (int c = 0; c < 2; c++) {
                    sc[f][c]   *= SM_SCALE;
                    sc[f][2+c] *= SM_SCALE;
                    r0max = fmaxf(r0max, sc[f][c]);
                    r1max = fmaxf(r1max, sc[f][2+c]);
                }
            }
        } else {
            #pragma unroll
            for (int f = 0; f < 8; f++) {
                int jb = jc + f*8 + tg*2;
                #pragma unroll
                for (int c = 0; c < 2; c++) {
                    int ja = jb + c;
                    bool ok0 = (ja <= tr0) && (ja > tr0 - WINDOW);
                    bool ok1 = (ja <= tr1) && (ja > tr1 - WINDOW);
                    sc[f][c]   = ok0 ? sc[f][c]*SM_SCALE   : -1e30f;
                    sc[f][2+c] = ok1 ? sc[f][2+c]*SM_SCALE : -1e30f;
                    r0max = fmaxf(r0max, sc[f][c]);
                    r1max = fmaxf(r1max, sc[f][2+c]);
                }
            }
        }
        r0max = fmaxf(r0max, __shfl_xor_sync(0xffffffffu, r0max, 1));
        r0max = fmaxf(r0max, __shfl_xor_sync(0xffffffffu, r0max, 2));
        r1max = fmaxf(r1max, __shfl_xor_sync(0xffffffffu, r1max, 1));
        r1max = fmaxf(r1max, __shfl_xor_sync(0xffffffffu, r1max, 2));
        float mc0 = fmaxf(m0, r0max), mc1 = fmaxf(m1, r1max);
        float ls0 = 0.0f, ls1 = 0.0f;
        if (interior) {
            #pragma unroll
            for (int f = 0; f < 8; f++) {
                #pragma unroll
                for (int c = 0; c < 2; c++) {
                    float p0 = __expf(sc[f][c]   - mc0);
                    float p1 = __expf(sc[f][2+c] - mc1);
                    sc[f][c] = p0; sc[f][2+c] = p1;
                    ls0 += p0; ls1 += p1;
                }
            }
        } else {
            #pragma unroll
            for (int f = 0; f < 8; f++) {
                #pragma unroll
                for (int c = 0; c < 2; c++) {
                    float p0 = (sc[f][c]   <= -1e29f) ? 0.0f : __expf(sc[f][c]   - mc0);
                    float p1 = (sc[f][2+c] <= -1e29f) ? 0.0f : __expf(sc[f][2+c] - mc1);
                    sc[f][c] = p0; sc[f][2+c] = p1;
                    ls0 += p0; ls1 += p1;
                }
            }
        }
        ls0 += __shfl_xor_sync(0xffffffffu, ls0, 1);
        ls0 += __shfl_xor_sync(0xffffffffu, ls0, 2);
        ls1 += __shfl_xor_sync(0xffffffffu, ls1, 1);
        ls1 += __shfl_xor_sync(0xffffffffu, ls1, 2);
        float s0 = __expf(m0 - mc0), s1 = __expf(m1 - mc1);
        l0 = l0*s0 + ls0; l1 = l1*s1 + ls1;
        m0 = mc0; m1 = mc1;

        #pragma unroll
        for (int f = 0; f < 16; f++) {
            o[f][0] *= s0; o[f][1] *= s0; o[f][2] *= s1; o[f][3] *= s1;
        }
        uint32_t pa[4][4];
        #pragma unroll
        for (int s = 0; s < 4; s++) {
            pa[s][0] = packbf(sc[2*s][0],   sc[2*s][1]);
            pa[s][1] = packbf(sc[2*s][2],   sc[2*s][3]);
            pa[s][2] = packbf(sc[2*s+1][0], sc[2*s+1][1]);
            pa[s][3] = packbf(sc[2*s+1][2], sc[2*s+1][3]);
        }
        {
            int vrow_b = ((lane >> 3) & 1)*8 + (lane & 7);
            int vcol_b = (lane >> 4)*8;
            #pragma unroll
            for (int s = 0; s < 4; s++) {
                #pragma unroll
                for (int ng = 0; ng < 8; ng++) {
                    uint32_t r0, r1, r2, r3;
                    ldsm_x4_t(r0, r1, r2, r3,
                              smem_u32(Vs + (s*16 + vrow_b)*FQP + ng*16 + vcol_b));
                    mma16816(o[2*ng],   pa[s], r0, r1);
                    mma16816(o[2*ng+1], pa[s], r2, r3);
                }
            }
        }
    }

    float inv0 = 1.0f / l0, inv1 = 1.0f / l1;
    __nv_bfloat16* ob0 = out16 + (size_t)(n0 + wrow + g)*HID + hh*DHEAD + tg*2;
    __nv_bfloat16* ob1 = out16 + (size_t)(n0 + wrow + 8 + g)*HID + hh*DHEAD + tg*2;
    #pragma unroll
    for (int f = 0; f < 16; f++) {
        *(uint32_t*)(ob0 + f*8) = packbf(o[f][0]*inv0, o[f][1]*inv0);
        *(uint32_t*)(ob1 + f*8) = packbf(o[f][2]*inv1, o[f][3]*inv1);
    }
}

// ---- residual + LayerNorm: warp-per-token ----
__global__ __launch_bounds__(256) void ln_kernel(float* __restrict__ x,
                                                 const float* __restrict__ add,
                                                 const float* __restrict__ g,
                                                 const float* __restrict__ b,
                                                 __nv_bfloat16* __restrict__ x16) {
    const int lane = threadIdx.x & 31;
    const int n = blockIdx.x*8 + (threadIdx.x >> 5);
    const size_t base = (size_t)n*HID;
    float v[4][4];
    float s = 0.0f, sq = 0.0f;
    #pragma unroll
    for (int k = 0; k < 4; k++) {
        int c = k*128 + lane*4;
        float4 t = *(const float4*)(x + base + c);
        if (add) {
            float4 a = *(const float4*)(add + base + c);
            t.x += a.x; t.y += a.y; t.z += a.z; t.w += a.w;
        }
        v[k][0]=t.x; v[k][1]=t.y; v[k][2]=t.z; v[k][3]=t.w;
        s  += t.x + t.y + t.z + t.w;
        sq += t.x*t.x + t.y*t.y + t.z*t.z + t.w*t.w;
    }
    #pragma unroll
    for (int o = 16; o > 0; o >>= 1) {
        s  += __shfl_xor_sync(0xffffffffu, s,  o);
        sq += __shfl_xor_sync(0xffffffffu, sq, o);
    }
    float mean = s * (1.0f/512.0f);
    float rstd = rsqrtf(sq * (1.0f/512.0f) - mean*mean + LN_EPS);
    #pragma unroll
    for (int k = 0; k < 4; k++) {
        int c = k*128 + lane*4;
        float4 gv = *(const float4*)(g + c);
        float4 bv = *(const float4*)(b + c);
        float o0 = (v[k][0] - mean)*rstd*gv.x + bv.x;
        float o1 = (v[k][1] - mean)*rstd*gv.y + bv.y;
        float o2 = (v[k][2] - mean)*rstd*gv.z + bv.z;
        float o3 = (v[k][3] - mean)*rstd*gv.w + bv.w;
        float4 of = {o0, o1, o2, o3};
        *(float4*)(x + base + c) = of;
        uint2 ob = {packbf(o0, o1), packbf(o2, o3)};
        *(uint2*)(x16 + base + c) = ob;
    }
}

// ---- loss ----
__global__ __launch_bounds__(1024) void loss_kernel(const float* __restrict__ yhat,
                                                    const float* __restrict__ y,
                                                    float* __restrict__ out) {
    float s = 0.0f;
    for (int e = threadIdx.x; e < NTOK*8; e += 1024) {
        int n = e >> 3, d = e & 7;
        int b = n >> 11, t = n & (SEQ - 1);
        float diff = yhat[e] - y[(size_t)(b*8 + d)*SEQ + t];
        s = fmaf(diff, diff, s);
    }
    #pragma unroll
    for (int o = 16; o > 0; o >>= 1) s += __shfl_xor_sync(0xffffffffu, s, o);
    __shared__ float red[32];
    int w = threadIdx.x >> 5;
    if ((threadIdx.x & 31) == 0) red[w] = s;
    __syncthreads();
    if (threadIdx.x == 0) {
        float tot = 0;
        #pragma unroll
        for (int i = 0; i < 32; i++) tot += red[i];
        out[0] = tot;
    }
}

// ---- host ----
static inline void run_wm(const __nv_bfloat16* A, const __nv_bfloat16* B, const float* bias,
                          float* C32, __nv_bfloat16* C16, int N, int K, int gelu) {
    gemm_bf16<<<dim3(N/128, NTOK/128), 256, GEMM_SMEM>>>(A, B, bias, C32, C16, N, K, gelu);
}

extern "C" void kernel_launch(void* const* d_in, const int* in_sizes, int n_in,
                              void* d_out, int out_size) {
    const float *u = (const float*)d_in[0], *y = (const float*)d_in[1];
    const float *W_in = (const float*)d_in[2], *b_in = (const float*)d_in[3];
    const float *qkv_w = (const float*)d_in[4], *qkv_b = (const float*)d_in[5];
    const float *out_w = (const float*)d_in[6], *out_b = (const float*)d_in[7];
    const float *ff1_w = (const float*)d_in[8], *ff1_b = (const float*)d_in[9];
    const float *ff2_w = (const float*)d_in[10], *ff2_b = (const float*)d_in[11];
    const float *ln1_g = (const float*)d_in[12], *ln1_b = (const float*)d_in[13];
    const float *ln2_g = (const float*)d_in[14], *ln2_b = (const float*)d_in[15];
    const float *lnf_g = (const float*)d_in[16], *lnf_b = (const float*)d_in[17];
    const float *xm1_w = (const float*)d_in[18], *xm1_b = (const float*)d_in[19];
    const float *xm2_w = (const float*)d_in[20], *xm2_b = (const float*)d_in[21];
    const float *me1_w = (const float*)d_in[22], *me1_b = (const float*)d_in[23];
    const float *me2_w = (const float*)d_in[24], *me2_b = (const float*)d_in[25];
    const float *me3_w = (const float*)d_in[26], *me3_b = (const float*)d_in[27];

    static float *px = nullptr, *pf32, *pt2, *psmall, *pyhat;
    static __nv_bfloat16 *pqkv16, *px16, *pattn16, *pmid16, *pwt;
    static cudaStream_t s2;
    static cudaEvent_t evA, evB;
    if (!px) {
        cudaGetSymbolAddress((void**)&px, g_x);
        cudaGetSymbolAddress((void**)&pf32, g_f32);
        cudaGetSymbolAddress((void**)&pt2, g_t2);
        cudaGetSymbolAddress((void**)&psmall, g_small);
        cudaGetSymbolAddress((void**)&pyhat, g_yhat);
        cudaGetSymbolAddress((void**)&pqkv16, g_qkv16);
        cudaGetSymbolAddress((void**)&px16, g_x16);
        cudaGetSymbolAddress((void**)&pattn16, g_attn16);
        cudaGetSymbolAddress((void**)&pmid16, g_mid16);
        cudaGetSymbolAddress((void**)&pwt, g_wt);
        cudaFuncSetAttribute(flash4, cudaFuncAttributeMaxDynamicSharedMemorySize, FLASH4_SMEM);
        cudaFuncSetAttribute(gemm_bf16, cudaFuncAttributeMaxDynamicSharedMemorySize, GEMM_SMEM);
        cudaStreamCreateWithFlags(&s2, cudaStreamNonBlocking);
        cudaEventCreateWithFlags(&evA, cudaEventDisableTiming);
        cudaEventCreateWithFlags(&evB, cudaEventDisableTiming);
    }

    dim3 tb(32, 8);
    // fork: non-QKV weight transposes on side stream, overlapped with layer-0 QKV+flash
    cudaEventRecord(evA, 0);
    cudaStreamWaitEvent(s2, evA, 0);
    wtrans<<<dim3(16, 16, 4), tb, 0, s2>>>(out_w, pwt + OFF_OUT, 512, 512);
    wtrans<<<dim3(16, 64, 4), tb, 0, s2>>>(ff1_w, pwt + OFF_FF1, 512, 2048);
    wtrans<<<dim3(64, 16, 4), tb, 0, s2>>>(ff2_w, pwt + OFF_FF2, 2048, 512);
    wtrans<<<dim3(16, 16, 1), tb, 0, s2>>>(xm1_w, pwt + OFF_XM1, 512, 512);
    wtrans<<<dim3(16, 16, 1), tb, 0, s2>>>(me2_w, pwt + OFF_ME2, 512, 512);
    cudaEventRecord(evB, s2);

    wtrans<<<dim3(16, 48, 4), tb>>>(qkv_w, pwt + OFF_QKV, 512, 1536);
    embed_kernel<<<NTOK, HID>>>(u, y, W_in, b_in, px, px16);

    for (int l = 0; l < NLAYER; l++) {
        run_wm(px16, pwt + OFF_QKV + (size_t)l*1536*512, qkv_b + l*1536, nullptr, pqkv16, 1536, 512, 0);
        flash4<<<dim3(NTOK/FQT, NHEAD), 256, FLASH4_SMEM>>>(pqkv16, pattn16);
        if (l == 0) cudaStreamWaitEvent(0, evB, 0);   // join before first out-proj use
        run_wm(pattn16, pwt + OFF_OUT + (size_t)l*512*512, out_b + l*512, pt2, nullptr, 512, 512, 0);
        ln_kernel<<<NTOK/8, 256>>>(px, pt2, ln1_g + l*HID, ln1_b + l*HID, px16);
        run_wm(px16, pwt + OFF_FF1 + (size_t)l*512*2048, ff1_b + l*2048, nullptr, pmid16, 2048, 512, 1);
        run_wm(pmid16, pwt + OFF_FF2 + (size_t)l*2048*512, ff2_b + l*512, pt2, nullptr, 512, 2048, 0);
        ln_kernel<<<NTOK/8, 256>>>(px, pt2, ln2_g + l*HID, ln2_b + l*HID, px16);
    }
    ln_kernel<<<NTOK/8, 256>>>(px, nullptr, lnf_g, lnf_b, px16);

    run_wm(px16, pwt + OFF_XM1, xm1_b, pt2, nullptr, 512, 512, 1);
    gemm_naive<<<NTOK*16/256, 256>>>(pt2, xm2_w, xm2_b, psmall, nullptr, 16, 512, 0);
    gemm_naive<<<NTOK*512/256, 256>>>(psmall, me1_w, me1_b, nullptr, pattn16, 512, 16, 1);
    run_wm(pattn16, pwt + OFF_ME2, me2_b, pf32, nullptr, 512, 512, 1);
    gemm_naive<<<NTOK*8/256, 256>>>(pf32, me3_w, me3_b, pyhat, nullptr, 8, 512, 0);

    loss_kernel<<<1, 1024>>>(pyhat, y, (float*)d_out);
}